// round 1
// baseline (speedup 1.0000x reference)
#include <cuda_runtime.h>
#include <cstdint>
#include <cstddef>

// Problem constants
#define BATCH   64
#define SEQ     2048
#define IDIM    256
#define HDIM    512
#define BDIM    256
#define INDIM   1280     // 3*IDIM + HDIM
#define XPART   768      // 3*IDIM
#define M_TOTAL (BATCH * SEQ)   // 131072
#define NG      1536     // 3 gates * HDIM

#define NBLK    128      // persistent recurrent grid (<= 148 SMs, 1 CTA/SM -> co-resident)

// -------------------- scratch (static __device__, allocation-free) --------------------
__device__ float g_XG[(size_t)M_TOTAL * NG];        // [m][1536]: xz | xr | xh pre-activations
__device__ float g_H [(size_t)SEQ * BATCH * HDIM];  // [t][b][j] hidden states after each step
__device__ float g_rh[BATCH * HDIM];                // [b][j] r*h exchange buffer (per step)
__device__ unsigned g_bar_count = 0;
__device__ unsigned g_bar_gen   = 0;

// -------------------- grid barrier (all NBLK CTAs co-resident) --------------------
__device__ __forceinline__ void grid_barrier() {
    __syncthreads();
    if (threadIdx.x == 0) {
        unsigned gen;
        asm volatile("ld.acquire.gpu.global.u32 %0, [%1];" : "=r"(gen) : "l"(&g_bar_gen));
        unsigned prev, one = 1u;
        asm volatile("atom.add.release.gpu.global.u32 %0, [%1], %2;"
                     : "=r"(prev) : "l"(&g_bar_count), "r"(one));
        if (prev == NBLK - 1) {
            unsigned dummy, zero = 0u;
            asm volatile("atom.exch.relaxed.gpu.global.b32 %0, [%1], %2;"
                         : "=r"(dummy) : "l"(&g_bar_count), "r"(zero));
            asm volatile("red.release.gpu.global.add.u32 [%0], %1;"
                         :: "l"(&g_bar_gen), "r"(one));
        } else {
            unsigned cur;
            do {
                asm volatile("ld.acquire.gpu.global.u32 %0, [%1];" : "=r"(cur) : "l"(&g_bar_gen));
            } while (cur == gen);
        }
    }
    __syncthreads();
}

// =====================================================================================
// Stage 1: XG[m][g*512+j] = bias_g[j] + sum_{k<768} xcat[m][k] * Wg[j][k]
//   m = t*64 + b ; xcat[m][k] = x[b][k>>8][t][k&255]
//   fp32 SIMT GEMM: BM=128, BN=128, BK=16, 256 threads, 8x8 per thread
// =====================================================================================
__global__ void __launch_bounds__(256) gemm_x_kernel(
    const float* __restrict__ x,
    const float* __restrict__ Wz, const float* __restrict__ Wr, const float* __restrict__ Wh,
    const float* __restrict__ bz, const float* __restrict__ br, const float* __restrict__ bh)
{
    __shared__ float As[16][132];
    __shared__ float Bs[16][132];
    const int tid  = threadIdx.x;
    const int m0   = blockIdx.x * 128;
    const int nblk = blockIdx.y * 128;            // 0..1535, 128-wide, tiles never cross a gate
    const int gate = nblk >> 9;
    const float* W    = (gate == 0) ? Wz : (gate == 1) ? Wr : Wh;
    const float* bias = (gate == 0) ? bz : (gate == 1) ? br : bh;
    const int n0 = nblk - (gate << 9);            // col within gate [0,512)
    const int tx = tid & 15, ty = tid >> 4;

    float acc[8][8];
    #pragma unroll
    for (int i = 0; i < 8; i++)
        #pragma unroll
        for (int j = 0; j < 8; j++) acc[i][j] = 0.f;

    for (int k0 = 0; k0 < XPART; k0 += 16) {
        #pragma unroll
        for (int i = 0; i < 2; i++) {
            int v  = tid + i * 256;               // 512 float4 loads per tile
            int ml = v >> 2;
            int kl = (v & 3) << 2;
            // A tile (gather from x): stays within one stream since 256 % 16 == 0
            int m = m0 + ml;
            int b = m & 63, t = m >> 6;
            int k = k0 + kl;
            int s = k >> 8, ii = k & 255;
            float4 a4 = *(const float4*)(x + (((size_t)(b * 3 + s)) * SEQ + t) * IDIM + ii);
            As[kl + 0][ml] = a4.x; As[kl + 1][ml] = a4.y;
            As[kl + 2][ml] = a4.z; As[kl + 3][ml] = a4.w;
            // B tile (weight rows, x-part columns)
            float4 b4 = *(const float4*)(W + (size_t)(n0 + ml) * INDIM + k);
            Bs[kl + 0][ml] = b4.x; Bs[kl + 1][ml] = b4.y;
            Bs[kl + 2][ml] = b4.z; Bs[kl + 3][ml] = b4.w;
        }
        __syncthreads();
        #pragma unroll
        for (int k = 0; k < 16; k++) {
            float4 a0  = *(const float4*)&As[k][ty * 8];
            float4 a1  = *(const float4*)&As[k][ty * 8 + 4];
            float4 bv0 = *(const float4*)&Bs[k][tx * 8];
            float4 bv1 = *(const float4*)&Bs[k][tx * 8 + 4];
            float av[8] = {a0.x, a0.y, a0.z, a0.w, a1.x, a1.y, a1.z, a1.w};
            float bw[8] = {bv0.x, bv0.y, bv0.z, bv0.w, bv1.x, bv1.y, bv1.z, bv1.w};
            #pragma unroll
            for (int i2 = 0; i2 < 8; i2++)
                #pragma unroll
                for (int j2 = 0; j2 < 8; j2++)
                    acc[i2][j2] += av[i2] * bw[j2];
        }
        __syncthreads();
    }
    #pragma unroll
    for (int i2 = 0; i2 < 8; i2++) {
        int m = m0 + ty * 8 + i2;
        float* dst = g_XG + (size_t)m * NG + nblk + tx * 8;
        #pragma unroll
        for (int j2 = 0; j2 < 8; j2++)
            dst[j2] = acc[i2][j2] + bias[n0 + tx * 8 + j2];
    }
}

// =====================================================================================
// Stage 2: persistent recurrent kernel.
//   Grid = 128 CTAs: blk -> (bslab = blk>>4, 8 batch rows) x (jslab = blk&15, 32 dims).
//   Thread (lane jl = tid&31, warp w = tid>>5): owns j = j0+jl, k-chunk [w*64, w*64+64).
//   Wz/Wr/Wh h-part slabs live in REGISTERS (3 x float4[16] per thread).
//   h / rh vectors staged in smem; per-thread partial dots reduced through smem.
//   Two grid barriers per step (publish r*h; publish h_new).
// =====================================================================================
__global__ void __launch_bounds__(256) recurrent_kernel(
    const float* __restrict__ Wz, const float* __restrict__ Wr, const float* __restrict__ Wh)
{
    extern __shared__ float sm[];
    float* h_s   = sm;            // 4096 floats: h_prev rows [8][512]
    float* rh_s  = sm + 4096;     // 4096 floats: r*h rows    [8][512]
    float* red_s = sm + 8192;     // 4096 floats: partials [gate][b][warp][jl]

    const int tid = threadIdx.x;
    const int jl  = tid & 31;
    const int w   = tid >> 5;
    const int blk = blockIdx.x;
    const int b0  = (blk >> 4) * 8;     // batch slab base
    const int j0  = (blk & 15) * 32;    // j slab base
    const int kb  = w * 64;             // k-chunk base

    // Load per-thread weight slabs into registers (h-part columns: offset XPART)
    float4 wz[16], wr[16], wh[16];
    {
        const float* pz = Wz + (size_t)(j0 + jl) * INDIM + XPART + kb;
        const float* pr = Wr + (size_t)(j0 + jl) * INDIM + XPART + kb;
        const float* ph = Wh + (size_t)(j0 + jl) * INDIM + XPART + kb;
        #pragma unroll
        for (int q = 0; q < 16; q++) {
            wz[q] = *(const float4*)(pz + q * 4);
            wr[q] = *(const float4*)(pr + q * 4);
            wh[q] = *(const float4*)(ph + q * 4);
        }
    }

    // combine-thread mapping: thread tid handles (cb = tid>>5, cj = tid&31)
    const int cb   = tid >> 5;
    const int cj   = tid & 31;
    const int gb_c = b0 + cb;          // global batch row
    const int j_c  = j0 + cj;          // global hidden dim
    float zv = 0.f, hpv = 0.f;         // persist across phases in registers

    for (int t = 0; t < SEQ; t++) {
        // ---- stage h_prev rows into smem ----
        if (t == 0) {
            for (int idx = tid; idx < 4096; idx += 256) h_s[idx] = 0.f;
        } else {
            const float* src = g_H + ((size_t)(t - 1) * BATCH + b0) * HDIM;
            for (int idx = tid * 4; idx < 4096; idx += 1024)
                *(float4*)&h_s[idx] = *(const float4*)&src[idx];
        }
        __syncthreads();

        // ---- phase A partial dots: z and r (h broadcast from smem, W from regs) ----
        #pragma unroll 1
        for (int b = 0; b < 8; b++) {
            float az = 0.f, ar = 0.f;
            const float* hb = h_s + b * 512 + kb;
            #pragma unroll
            for (int q = 0; q < 16; q++) {
                float4 h4 = *(const float4*)(hb + q * 4);   // same addr across lanes: broadcast
                az += wz[q].x * h4.x + wz[q].y * h4.y + wz[q].z * h4.z + wz[q].w * h4.w;
                ar += wr[q].x * h4.x + wr[q].y * h4.y + wr[q].z * h4.z + wr[q].w * h4.w;
            }
            red_s[((0 * 8 + b) * 8 + w) * 32 + jl] = az;
            red_s[((1 * 8 + b) * 8 + w) * 32 + jl] = ar;
        }
        __syncthreads();

        // ---- combine A: reduce 8 k-chunks, apply sigmoid, publish r*h ----
        {
            float sz = 0.f, sr = 0.f;
            #pragma unroll
            for (int u = 0; u < 8; u++) {
                sz += red_s[((0 * 8 + cb) * 8 + u) * 32 + cj];
                sr += red_s[((1 * 8 + cb) * 8 + u) * 32 + cj];
            }
            const size_t m = (size_t)t * BATCH + gb_c;
            float xz = g_XG[m * NG + j_c];
            float xr = g_XG[m * NG + 512 + j_c];
            zv  = 1.f / (1.f + expf(-(xz + sz)));
            float rv = 1.f / (1.f + expf(-(xr + sr)));
            hpv = h_s[cb * 512 + j_c];
            g_rh[(size_t)gb_c * HDIM + j_c] = rv * hpv;
        }
        grid_barrier();   // r*h from all j-slabs visible

        // ---- stage rh rows ----
        {
            const float* src = g_rh + (size_t)b0 * HDIM;
            for (int idx = tid * 4; idx < 4096; idx += 1024)
                *(float4*)&rh_s[idx] = *(const float4*)&src[idx];
        }
        __syncthreads();

        // ---- phase B partial dots: h_tilde ----
        #pragma unroll 1
        for (int b = 0; b < 8; b++) {
            float ah = 0.f;
            const float* rb = rh_s + b * 512 + kb;
            #pragma unroll
            for (int q = 0; q < 16; q++) {
                float4 r4 = *(const float4*)(rb + q * 4);
                ah += wh[q].x * r4.x + wh[q].y * r4.y + wh[q].z * r4.z + wh[q].w * r4.w;
            }
            red_s[(b * 8 + w) * 32 + jl] = ah;
        }
        __syncthreads();

        // ---- combine B: tanh, gate, publish h_new ----
        {
            float sh = 0.f;
            #pragma unroll
            for (int u = 0; u < 8; u++) sh += red_s[(cb * 8 + u) * 32 + cj];
            const size_t m = (size_t)t * BATCH + gb_c;
            float xh = g_XG[m * NG + 1024 + j_c];
            float ht = tanhf(xh + sh);
            float hn = hpv + zv * (ht - hpv);   // (1-z)h + z*h_tilde
            g_H[m * HDIM + j_c] = hn;
        }
        grid_barrier();   // h_new visible to all CTAs; rh/red buffers safe to reuse
    }
}

// =====================================================================================
// Stage 3: out[b][t][c] = bb[c] + sum_j g_H[t][b][j] * Wb[c][j]
// =====================================================================================
__global__ void __launch_bounds__(256) gemm_b_kernel(
    const float* __restrict__ Wb, const float* __restrict__ bb, float* __restrict__ out)
{
    __shared__ float As[16][132];
    __shared__ float Bs[16][132];
    const int tid = threadIdx.x;
    const int m0  = blockIdx.x * 128;
    const int n0  = blockIdx.y * 128;
    const int tx = tid & 15, ty = tid >> 4;

    float acc[8][8];
    #pragma unroll
    for (int i = 0; i < 8; i++)
        #pragma unroll
        for (int j = 0; j < 8; j++) acc[i][j] = 0.f;

    for (int k0 = 0; k0 < HDIM; k0 += 16) {
        #pragma unroll
        for (int i = 0; i < 2; i++) {
            int v  = tid + i * 256;
            int ml = v >> 2;
            int kl = (v & 3) << 2;
            float4 a4 = *(const float4*)(g_H + (size_t)(m0 + ml) * HDIM + k0 + kl);
            As[kl + 0][ml] = a4.x; As[kl + 1][ml] = a4.y;
            As[kl + 2][ml] = a4.z; As[kl + 3][ml] = a4.w;
            float4 b4 = *(const float4*)(Wb + (size_t)(n0 + ml) * HDIM + k0 + kl);
            Bs[kl + 0][ml] = b4.x; Bs[kl + 1][ml] = b4.y;
            Bs[kl + 2][ml] = b4.z; Bs[kl + 3][ml] = b4.w;
        }
        __syncthreads();
        #pragma unroll
        for (int k = 0; k < 16; k++) {
            float4 a0  = *(const float4*)&As[k][ty * 8];
            float4 a1  = *(const float4*)&As[k][ty * 8 + 4];
            float4 bv0 = *(const float4*)&Bs[k][tx * 8];
            float4 bv1 = *(const float4*)&Bs[k][tx * 8 + 4];
            float av[8] = {a0.x, a0.y, a0.z, a0.w, a1.x, a1.y, a1.z, a1.w};
            float bw[8] = {bv0.x, bv0.y, bv0.z, bv0.w, bv1.x, bv1.y, bv1.z, bv1.w};
            #pragma unroll
            for (int i2 = 0; i2 < 8; i2++)
                #pragma unroll
                for (int j2 = 0; j2 < 8; j2++)
                    acc[i2][j2] += av[i2] * bw[j2];
        }
        __syncthreads();
    }
    #pragma unroll
    for (int i2 = 0; i2 < 8; i2++) {
        int m = m0 + ty * 8 + i2;
        int b = m & 63, t = m >> 6;
        float* dst = out + ((size_t)b * SEQ + t) * BDIM + n0 + tx * 8;
        #pragma unroll
        for (int j2 = 0; j2 < 8; j2++)
            dst[j2] = acc[i2][j2] + bb[n0 + tx * 8 + j2];
    }
}

// Final hidden state: out[B*T*256 + b*512 + j] = g_H[T-1][b][j] (contiguous block)
__global__ void hfin_kernel(float* __restrict__ out)
{
    int i = blockIdx.x * blockDim.x + threadIdx.x;
    if (i < BATCH * HDIM)
        out[(size_t)BATCH * SEQ * BDIM + i] = g_H[(size_t)(SEQ - 1) * BATCH * HDIM + i];
}

// =====================================================================================
extern "C" void kernel_launch(void* const* d_in, const int* in_sizes, int n_in,
                              void* d_out, int out_size)
{
    (void)in_sizes; (void)n_in; (void)out_size;
    const float* x  = (const float*)d_in[0];
    const float* Wz = (const float*)d_in[1];
    const float* bz = (const float*)d_in[2];
    const float* Wr = (const float*)d_in[3];
    const float* br = (const float*)d_in[4];
    const float* Wh = (const float*)d_in[5];
    const float* bh = (const float*)d_in[6];
    const float* Wb = (const float*)d_in[7];
    const float* bb = (const float*)d_in[8];
    float* out = (float*)d_out;

    // Stage 1: x-part pre-activations for all (t, b), all 3 gates
    dim3 g1(M_TOTAL / 128, NG / 128);
    gemm_x_kernel<<<g1, 256>>>(x, Wz, Wr, Wh, bz, br, bh);

    // Stage 2: persistent recurrence (48 KB dynamic smem, within default limit)
    recurrent_kernel<<<NBLK, 256, 12288 * sizeof(float)>>>(Wz, Wr, Wh);

    // Stage 3: output projection for all timesteps + final hidden state
    dim3 g3(M_TOTAL / 128, BDIM / 128);
    gemm_b_kernel<<<g3, 256>>>(Wb, bb, out);
    hfin_kernel<<<(BATCH * HDIM + 255) / 256, 256>>>(out);
}

// round 3
// speedup vs baseline: 1.1315x; 1.1315x over previous
#include <cuda_runtime.h>
#include <cuda_bf16.h>
#include <cstdint>
#include <cstddef>

// Problem constants
#define BATCH   64
#define SEQ     2048
#define IDIM    256
#define HDIM    512
#define BDIM    256
#define INDIM   1280     // 3*IDIM + HDIM
#define XPART   768      // 3*IDIM
#define M_TOTAL (BATCH * SEQ)   // 131072
#define NG      1536     // 3 gates * HDIM

#define NBLK    128      // persistent recurrent grid (1 CTA/SM -> co-resident)

// -------------------- scratch (static __device__, allocation-free) --------------------
__device__ float g_XG[(size_t)M_TOTAL * NG];        // [b*SEQ+t][1536]: xz | xr | xh pre-activations
__device__ float g_H [(size_t)SEQ * BATCH * HDIM];  // [t][b][j] hidden states after each step
__device__ float g_rh[BATCH * HDIM];                // [b][j] r*h exchange buffer (per step)
__device__ unsigned g_bar_count = 0;
__device__ unsigned g_bar_gen   = 0;

// bf16 split operands
__device__ __nv_bfloat16 g_Xh[(size_t)M_TOTAL * XPART];   // x concat, hi part, [b*SEQ+t][768]
__device__ __nv_bfloat16 g_Xl[(size_t)M_TOTAL * XPART];   // lo part
__device__ __nv_bfloat16 g_Wxh[(size_t)NG * XPART];       // [1536][768] x-part of Wz|Wr|Wh
__device__ __nv_bfloat16 g_Wxl[(size_t)NG * XPART];
__device__ __nv_bfloat16 g_Hh[(size_t)M_TOTAL * HDIM];    // hidden states, [b*SEQ+t][512]
__device__ __nv_bfloat16 g_Hl[(size_t)M_TOTAL * HDIM];
__device__ __nv_bfloat16 g_Wbh[(size_t)BDIM * HDIM];
__device__ __nv_bfloat16 g_Wbl[(size_t)BDIM * HDIM];
__device__ float g_bcat[NG];

// =====================================================================================
// Prep kernels: build bf16 hi/lo split operands
// =====================================================================================
__global__ void __launch_bounds__(256) prep_wx_kernel(
    const float* __restrict__ Wz, const float* __restrict__ Wr, const float* __restrict__ Wh,
    const float* __restrict__ bz, const float* __restrict__ br, const float* __restrict__ bh)
{
    int idx = blockIdx.x * 256 + threadIdx.x;
    if (idx < NG * XPART) {
        int j = idx / XPART, k = idx - j * XPART;
        int gate = j >> 9, jj = j & 511;
        const float* W = (gate == 0) ? Wz : (gate == 1) ? Wr : Wh;
        float v = W[(size_t)jj * INDIM + k];
        __nv_bfloat16 hi = __float2bfloat16(v);
        __nv_bfloat16 lo = __float2bfloat16(v - __bfloat162float(hi));
        g_Wxh[idx] = hi; g_Wxl[idx] = lo;
    }
    if (idx < NG) {
        g_bcat[idx] = (idx < 512) ? bz[idx] : (idx < 1024) ? br[idx - 512] : bh[idx - 1024];
    }
}

__global__ void __launch_bounds__(256) prep_wb_kernel(const float* __restrict__ Wb)
{
    int idx = blockIdx.x * 256 + threadIdx.x;
    if (idx < BDIM * HDIM) {
        float v = Wb[idx];
        __nv_bfloat16 hi = __float2bfloat16(v);
        __nv_bfloat16 lo = __float2bfloat16(v - __bfloat162float(hi));
        g_Wbh[idx] = hi; g_Wbl[idx] = lo;
    }
}

// x (b, s, t, i) -> Xh/Xl[(b*SEQ+t)*768 + s*256 + i], hi/lo bf16 split
__global__ void __launch_bounds__(256) prep_x_kernel(const float* __restrict__ x)
{
    int idx = blockIdx.x * 256 + threadIdx.x;      // one float4
    size_t e = (size_t)idx * 4;
    int b = (int)(e / 1572864);                    // 3*2048*256
    int r = (int)(e - (size_t)b * 1572864);
    int s = r / 524288;                            // 2048*256
    int r2 = r - s * 524288;
    int t = r2 >> 8, i = r2 & 255;
    float4 v = *(const float4*)(x + e);
    size_t dst = ((size_t)b * SEQ + t) * XPART + s * 256 + i;
    __nv_bfloat16 hx = __float2bfloat16(v.x), hy = __float2bfloat16(v.y);
    __nv_bfloat16 hz = __float2bfloat16(v.z), hw = __float2bfloat16(v.w);
    *(__nv_bfloat162*)(g_Xh + dst)     = __nv_bfloat162(hx, hy);
    *(__nv_bfloat162*)(g_Xh + dst + 2) = __nv_bfloat162(hz, hw);
    *(__nv_bfloat162*)(g_Xl + dst)     = __nv_bfloat162(
        __float2bfloat16(v.x - __bfloat162float(hx)), __float2bfloat16(v.y - __bfloat162float(hy)));
    *(__nv_bfloat162*)(g_Xl + dst + 2) = __nv_bfloat162(
        __float2bfloat16(v.z - __bfloat162float(hz)), __float2bfloat16(v.w - __bfloat162float(hw)));
}

// g_H[t][b][j] -> Hh/Hl[(b*SEQ+t)*512 + j]
__global__ void __launch_bounds__(256) prep_h_kernel()
{
    int idx = blockIdx.x * 256 + threadIdx.x;
    size_t e = (size_t)idx * 4;
    int mp = (int)(e >> 9);                        // b*SEQ+t
    int j  = (int)(e & 511);
    int b = mp >> 11, t = mp & 2047;
    float4 v = *(const float4*)(g_H + (((size_t)t * BATCH + b) << 9) + j);
    __nv_bfloat16 hx = __float2bfloat16(v.x), hy = __float2bfloat16(v.y);
    __nv_bfloat16 hz = __float2bfloat16(v.z), hw = __float2bfloat16(v.w);
    *(__nv_bfloat162*)(g_Hh + e)     = __nv_bfloat162(hx, hy);
    *(__nv_bfloat162*)(g_Hh + e + 2) = __nv_bfloat162(hz, hw);
    *(__nv_bfloat162*)(g_Hl + e)     = __nv_bfloat162(
        __float2bfloat16(v.x - __bfloat162float(hx)), __float2bfloat16(v.y - __bfloat162float(hy)));
    *(__nv_bfloat162*)(g_Hl + e + 2) = __nv_bfloat162(
        __float2bfloat16(v.z - __bfloat162float(hz)), __float2bfloat16(v.w - __bfloat162float(hw)));
}

// =====================================================================================
// mma.sync bf16 GEMM (portable: no tcgen05).  C[m][n] = bias[n] + sum_k A[m][k]*B[n][k]
//   augmented K: Ah*Bh + Ah*Bl + Al*Bh  (phases over 32-wide K chunks)
//   Tile 128x128xBK32, 8 warps (4M x 2N), warp tile 32x64, m16n8k16 fragments.
// =====================================================================================
#define LDM_X4(r0, r1, r2, r3, a) \
    asm volatile("ldmatrix.sync.aligned.m8n8.x4.shared.b16 {%0,%1,%2,%3}, [%4];" \
                 : "=r"(r0), "=r"(r1), "=r"(r2), "=r"(r3) : "r"(a))

#define MMA16816(d, a, b) \
    asm volatile("mma.sync.aligned.m16n8k16.row.col.f32.bf16.bf16.f32 " \
                 "{%0,%1,%2,%3}, {%4,%5,%6,%7}, {%8,%9}, {%0,%1,%2,%3};" \
                 : "+f"((d)[0]), "+f"((d)[1]), "+f"((d)[2]), "+f"((d)[3]) \
                 : "r"((a)[0]), "r"((a)[1]), "r"((a)[2]), "r"((a)[3]), \
                   "r"((b)[0]), "r"((b)[1]))

#define SMSTRIDE 40   // bf16 elements per smem row (32 data + 8 pad); 80 B, 16B-aligned

__global__ void __launch_bounds__(256) gemm_mma_kernel(
    const __nv_bfloat16* __restrict__ Ah, const __nv_bfloat16* __restrict__ Al, int lda,
    const __nv_bfloat16* __restrict__ Bh, const __nv_bfloat16* __restrict__ Bl, int ldb,
    const float* __restrict__ bias, float* __restrict__ C, int ldc, int K32)
{
    __shared__ __align__(16) __nv_bfloat16 As[128][SMSTRIDE];
    __shared__ __align__(16) __nv_bfloat16 Bs[128][SMSTRIDE];

    const int tid  = threadIdx.x;
    const int wid  = tid >> 5;
    const int lane = tid & 31;
    const int n0   = blockIdx.x * 128;
    const int m0   = blockIdx.y * 128;
    const int m0w  = (wid & 3) * 32;     // warp M origin within tile
    const int n0w  = (wid >> 2) * 64;    // warp N origin within tile

    // global-load mapping: 2 uint4 per thread (row, 8-elem column group)
    const int gr0 = (tid * 2) >> 2,     gc0 = ((tid * 2) & 3) * 8;
    const int gr1 = (tid * 2 + 1) >> 2, gc1 = ((tid * 2 + 1) & 3) * 8;

    // ldmatrix per-lane address components
    uint32_t sA, sB;
    asm("{ .reg .u64 t; cvta.to.shared.u64 t, %1; cvt.u32.u64 %0, t; }" : "=r"(sA) : "l"(&As[0][0]));
    asm("{ .reg .u64 t; cvta.to.shared.u64 t, %1; cvt.u32.u64 %0, t; }" : "=r"(sB) : "l"(&Bs[0][0]));
    const int a_row = m0w + (lane & 7) + ((lane >> 3) & 1) * 8;   // + mb*16
    const int a_kof = ((lane >> 4) & 1) * 8;                      // + ks*16
    const int b_row = n0w + (lane & 7) + ((lane >> 4) & 1) * 8;   // + q*16
    const int b_kof = ((lane >> 3) & 1) * 8;                      // + ks*16

    float acc[2][8][4];
    #pragma unroll
    for (int i = 0; i < 2; i++)
        #pragma unroll
        for (int j = 0; j < 8; j++)
            #pragma unroll
            for (int q = 0; q < 4; q++) acc[i][j][q] = 0.f;

    const int NC = 3 * K32;
    uint4 pa0, pa1, pb0, pb1;

    // prefetch chunk 0
    {
        const __nv_bfloat16* Asrc = Ah;
        const __nv_bfloat16* Bsrc = Bh;
        pa0 = *(const uint4*)(Asrc + (size_t)(m0 + gr0) * lda + gc0);
        pa1 = *(const uint4*)(Asrc + (size_t)(m0 + gr1) * lda + gc1);
        pb0 = *(const uint4*)(Bsrc + (size_t)(n0 + gr0) * ldb + gc0);
        pb1 = *(const uint4*)(Bsrc + (size_t)(n0 + gr1) * ldb + gc1);
    }

    #pragma unroll 1
    for (int c = 0; c < NC; c++) {
        // commit prefetched chunk to smem
        *(uint4*)&As[gr0][gc0] = pa0;
        *(uint4*)&As[gr1][gc1] = pa1;
        *(uint4*)&Bs[gr0][gc0] = pb0;
        *(uint4*)&Bs[gr1][gc1] = pb1;
        __syncthreads();

        // issue next chunk's global loads
        if (c + 1 < NC) {
            const int cn = c + 1;
            const int ph = cn / K32;
            const int kk = (cn - ph * K32) * 32;
            const __nv_bfloat16* Asrc = (ph < 2) ? Ah : Al;
            const __nv_bfloat16* Bsrc = (ph == 1) ? Bl : Bh;
            pa0 = *(const uint4*)(Asrc + (size_t)(m0 + gr0) * lda + kk + gc0);
            pa1 = *(const uint4*)(Asrc + (size_t)(m0 + gr1) * lda + kk + gc1);
            pb0 = *(const uint4*)(Bsrc + (size_t)(n0 + gr0) * ldb + kk + gc0);
            pb1 = *(const uint4*)(Bsrc + (size_t)(n0 + gr1) * ldb + kk + gc1);
        }

        // compute on current smem chunk: 2 k16-steps
        #pragma unroll
        for (int ks = 0; ks < 2; ks++) {
            uint32_t af[2][4];
            #pragma unroll
            for (int mb = 0; mb < 2; mb++) {
                uint32_t ad = sA + (uint32_t)((a_row + mb * 16) * (SMSTRIDE * 2)
                                              + (ks * 16 + a_kof) * 2);
                LDM_X4(af[mb][0], af[mb][1], af[mb][2], af[mb][3], ad);
            }
            uint32_t bf[8][2];
            #pragma unroll
            for (int q = 0; q < 4; q++) {
                uint32_t bd = sB + (uint32_t)((b_row + q * 16) * (SMSTRIDE * 2)
                                              + (ks * 16 + b_kof) * 2);
                LDM_X4(bf[2 * q][0], bf[2 * q][1], bf[2 * q + 1][0], bf[2 * q + 1][1], bd);
            }
            #pragma unroll
            for (int mb = 0; mb < 2; mb++)
                #pragma unroll
                for (int nb = 0; nb < 8; nb++)
                    MMA16816(acc[mb][nb], af[mb], bf[nb]);
        }
        __syncthreads();
    }

    // epilogue: c-frag rows = g, g+8; cols = 2*tig, +1
    const int g   = lane >> 2;
    const int tig = lane & 3;
    #pragma unroll
    for (int mb = 0; mb < 2; mb++) {
        #pragma unroll
        for (int nb = 0; nb < 8; nb++) {
            int col = n0 + n0w + nb * 8 + tig * 2;
            float b0 = bias[col], b1 = bias[col + 1];
            int r0 = m0 + m0w + mb * 16 + g;
            *(float2*)(C + (size_t)r0 * ldc + col) =
                make_float2(acc[mb][nb][0] + b0, acc[mb][nb][1] + b1);
            *(float2*)(C + (size_t)(r0 + 8) * ldc + col) =
                make_float2(acc[mb][nb][2] + b0, acc[mb][nb][3] + b1);
        }
    }
}

// =====================================================================================
// grid barrier (all NBLK CTAs co-resident)
// =====================================================================================
__device__ __forceinline__ void grid_barrier() {
    __syncthreads();
    if (threadIdx.x == 0) {
        unsigned gen;
        asm volatile("ld.acquire.gpu.global.u32 %0, [%1];" : "=r"(gen) : "l"(&g_bar_gen));
        unsigned prev, one = 1u;
        asm volatile("atom.add.release.gpu.global.u32 %0, [%1], %2;"
                     : "=r"(prev) : "l"(&g_bar_count), "r"(one));
        if (prev == NBLK - 1) {
            unsigned dummy, zero = 0u;
            asm volatile("atom.exch.relaxed.gpu.global.b32 %0, [%1], %2;"
                         : "=r"(dummy) : "l"(&g_bar_count), "r"(zero));
            asm volatile("red.release.gpu.global.add.u32 [%0], %1;"
                         :: "l"(&g_bar_gen), "r"(one));
        } else {
            unsigned cur;
            do {
                asm volatile("ld.acquire.gpu.global.u32 %0, [%1];" : "=r"(cur) : "l"(&g_bar_gen));
            } while (cur == gen);
        }
    }
    __syncthreads();
}

// =====================================================================================
// Stage 2: persistent recurrent kernel
// =====================================================================================
__global__ void __launch_bounds__(256) recurrent_kernel(
    const float* __restrict__ Wz, const float* __restrict__ Wr, const float* __restrict__ Wh)
{
    extern __shared__ float sm[];
    float* h_s   = sm;            // 4096 floats: h_prev rows [8][512]
    float* rh_s  = sm + 4096;     // 4096 floats: r*h rows    [8][512]
    float* red_s = sm + 8192;     // 4096 floats: partials [gate][b][warp][jl]

    const int tid = threadIdx.x;
    const int jl  = tid & 31;
    const int w   = tid >> 5;
    const int blk = blockIdx.x;
    const int b0  = (blk >> 4) * 8;
    const int j0  = (blk & 15) * 32;
    const int kb  = w * 64;

    float4 wz[16], wr[16], wh[16];
    {
        const float* pz = Wz + (size_t)(j0 + jl) * INDIM + XPART + kb;
        const float* pr = Wr + (size_t)(j0 + jl) * INDIM + XPART + kb;
        const float* ph = Wh + (size_t)(j0 + jl) * INDIM + XPART + kb;
        #pragma unroll
        for (int q = 0; q < 16; q++) {
            wz[q] = *(const float4*)(pz + q * 4);
            wr[q] = *(const float4*)(pr + q * 4);
            wh[q] = *(const float4*)(ph + q * 4);
        }
    }

    const int cb   = tid >> 5;
    const int cj   = tid & 31;
    const int gb_c = b0 + cb;
    const int j_c  = j0 + cj;
    float zv = 0.f, hpv = 0.f;

    for (int t = 0; t < SEQ; t++) {
        if (t == 0) {
            for (int idx = tid; idx < 4096; idx += 256) h_s[idx] = 0.f;
        } else {
            const float* src = g_H + ((size_t)(t - 1) * BATCH + b0) * HDIM;
            for (int idx = tid * 4; idx < 4096; idx += 1024)
                *(float4*)&h_s[idx] = *(const float4*)&src[idx];
        }
        __syncthreads();

        #pragma unroll 1
        for (int b = 0; b < 8; b++) {
            float az = 0.f, ar = 0.f;
            const float* hb = h_s + b * 512 + kb;
            #pragma unroll
            for (int q = 0; q < 16; q++) {
                float4 h4 = *(const float4*)(hb + q * 4);
                az += wz[q].x * h4.x + wz[q].y * h4.y + wz[q].z * h4.z + wz[q].w * h4.w;
                ar += wr[q].x * h4.x + wr[q].y * h4.y + wr[q].z * h4.z + wr[q].w * h4.w;
            }
            red_s[((0 * 8 + b) * 8 + w) * 32 + jl] = az;
            red_s[((1 * 8 + b) * 8 + w) * 32 + jl] = ar;
        }
        __syncthreads();

        {
            float sz = 0.f, sr = 0.f;
            #pragma unroll
            for (int u = 0; u < 8; u++) {
                sz += red_s[((0 * 8 + cb) * 8 + u) * 32 + cj];
                sr += red_s[((1 * 8 + cb) * 8 + u) * 32 + cj];
            }
            const size_t xrow = (size_t)gb_c * SEQ + t;   // b-major XG layout
            float xz = g_XG[xrow * NG + j_c];
            float xr = g_XG[xrow * NG + 512 + j_c];
            zv  = 1.f / (1.f + expf(-(xz + sz)));
            float rv = 1.f / (1.f + expf(-(xr + sr)));
            hpv = h_s[cb * 512 + j_c];
            g_rh[(size_t)gb_c * HDIM + j_c] = rv * hpv;
        }
        grid_barrier();

        {
            const float* src = g_rh + (size_t)b0 * HDIM;
            for (int idx = tid * 4; idx < 4096; idx += 1024)
                *(float4*)&rh_s[idx] = *(const float4*)&src[idx];
        }
        __syncthreads();

        #pragma unroll 1
        for (int b = 0; b < 8; b++) {
            float ah = 0.f;
            const float* rb = rh_s + b * 512 + kb;
            #pragma unroll
            for (int q = 0; q < 16; q++) {
                float4 r4 = *(const float4*)(rb + q * 4);
                ah += wh[q].x * r4.x + wh[q].y * r4.y + wh[q].z * r4.z + wh[q].w * r4.w;
            }
            red_s[(b * 8 + w) * 32 + jl] = ah;
        }
        __syncthreads();

        {
            float sh = 0.f;
            #pragma unroll
            for (int u = 0; u < 8; u++) sh += red_s[(cb * 8 + u) * 32 + cj];
            const size_t xrow = (size_t)gb_c * SEQ + t;
            float xh = g_XG[xrow * NG + 1024 + j_c];
            float ht = tanhf(xh + sh);
            float hn = hpv + zv * (ht - hpv);
            g_H[((size_t)t * BATCH + gb_c) * HDIM + j_c] = hn;
        }
        grid_barrier();
    }
}

// Final hidden state
__global__ void hfin_kernel(float* __restrict__ out)
{
    int i = blockIdx.x * blockDim.x + threadIdx.x;
    if (i < BATCH * HDIM)
        out[(size_t)BATCH * SEQ * BDIM + i] = g_H[(size_t)(SEQ - 1) * BATCH * HDIM + i];
}

// =====================================================================================
extern "C" void kernel_launch(void* const* d_in, const int* in_sizes, int n_in,
                              void* d_out, int out_size)
{
    (void)in_sizes; (void)n_in; (void)out_size;
    const float* x  = (const float*)d_in[0];
    const float* Wz = (const float*)d_in[1];
    const float* bz = (const float*)d_in[2];
    const float* Wr = (const float*)d_in[3];
    const float* br = (const float*)d_in[4];
    const float* Wh = (const float*)d_in[5];
    const float* bh = (const float*)d_in[6];
    const float* Wb = (const float*)d_in[7];
    const float* bb = (const float*)d_in[8];
    float* out = (float*)d_out;

    // resolve device symbol addresses for gemm args (host-side query; capture-safe)
    __nv_bfloat16 *Xh, *Xl, *Wxh, *Wxl, *Hh, *Hl, *Wbh, *Wbl;
    float *XG, *bcat;
    cudaGetSymbolAddress((void**)&Xh,  g_Xh);
    cudaGetSymbolAddress((void**)&Xl,  g_Xl);
    cudaGetSymbolAddress((void**)&Wxh, g_Wxh);
    cudaGetSymbolAddress((void**)&Wxl, g_Wxl);
    cudaGetSymbolAddress((void**)&Hh,  g_Hh);
    cudaGetSymbolAddress((void**)&Hl,  g_Hl);
    cudaGetSymbolAddress((void**)&Wbh, g_Wbh);
    cudaGetSymbolAddress((void**)&Wbl, g_Wbl);
    cudaGetSymbolAddress((void**)&XG,  g_XG);
    cudaGetSymbolAddress((void**)&bcat, g_bcat);

    // Prep: bf16 hi/lo splits
    prep_wx_kernel<<<(NG * XPART + 255) / 256, 256>>>(Wz, Wr, Wh, bz, br, bh);
    prep_wb_kernel<<<(BDIM * HDIM + 255) / 256, 256>>>(Wb);
    prep_x_kernel<<<(M_TOTAL * XPART / 4) / 256, 256>>>(x);

    // Stage 1: XG = xcat @ Wx^T + bcat   (mma.sync split-bf16)
    gemm_mma_kernel<<<dim3(NG / 128, M_TOTAL / 128), 256>>>(
        Xh, Xl, XPART, Wxh, Wxl, XPART, bcat, XG, NG, XPART / 32);

    // Stage 2: persistent recurrence
    recurrent_kernel<<<NBLK, 256, 12288 * sizeof(float)>>>(Wz, Wr, Wh);

    // Stage 3: out = H @ Wb^T + bb   (mma.sync split-bf16)
    prep_h_kernel<<<(M_TOTAL * HDIM / 4) / 256, 256>>>();
    gemm_mma_kernel<<<dim3(BDIM / 128, M_TOTAL / 128), 256>>>(
        Hh, Hl, HDIM, Wbh, Wbl, HDIM, bb, out, BDIM, HDIM / 32);

    hfin_kernel<<<(BATCH * HDIM + 255) / 256, 256>>>(out);
}

// round 4
// speedup vs baseline: 1.6005x; 1.4145x over previous
#include <cuda_runtime.h>
#include <cuda_bf16.h>
#include <cstdint>
#include <cstddef>

// Problem constants
#define BATCH   64
#define SEQ     2048
#define IDIM    256
#define HDIM    512
#define BDIM    256
#define INDIM   1280     // 3*IDIM + HDIM
#define XPART   768      // 3*IDIM
#define M_TOTAL (BATCH * SEQ)   // 131072
#define NG      1536     // 3 gates * HDIM

#define NBLK2   128      // persistent recurrent grid (1 CTA/SM -> co-resident)

// -------------------- scratch (static __device__, allocation-free) --------------------
__device__ float g_XG[(size_t)M_TOTAL * NG];        // [b*SEQ+t][1536]: xz | xr | xh pre-acts
__device__ unsigned g_cnt;                          // monotonic grid-barrier counter

// packed bf16 hi|lo exchange buffers (u32 = hi | lo<<16)
__device__ unsigned g_hpk [BATCH * HDIM];           // h_t
__device__ unsigned g_rhpk[BATCH * HDIM];           // r*h

// bf16 split operands
__device__ __nv_bfloat16 g_Xh[(size_t)M_TOTAL * XPART];   // x concat hi, [b*SEQ+t][768]
__device__ __nv_bfloat16 g_Xl[(size_t)M_TOTAL * XPART];
__device__ __nv_bfloat16 g_Wxh[(size_t)NG * XPART];       // [1536][768] x-part of Wz|Wr|Wh
__device__ __nv_bfloat16 g_Wxl[(size_t)NG * XPART];
__device__ __nv_bfloat16 g_Hh[(size_t)M_TOTAL * HDIM];    // hidden states, [b*SEQ+t][512]
__device__ __nv_bfloat16 g_Hl[(size_t)M_TOTAL * HDIM];
__device__ __nv_bfloat16 g_Wbh[(size_t)BDIM * HDIM];
__device__ __nv_bfloat16 g_Wbl[(size_t)BDIM * HDIM];
__device__ float g_bcat[NG];

// =====================================================================================
// MMA / ldmatrix macros (portable sm_80+ PTX)
// =====================================================================================
#define LDM_X4(r0, r1, r2, r3, a) \
    asm volatile("ldmatrix.sync.aligned.m8n8.x4.shared.b16 {%0,%1,%2,%3}, [%4];" \
                 : "=r"(r0), "=r"(r1), "=r"(r2), "=r"(r3) : "r"(a))
#define LDM_X2(r0, r1, a) \
    asm volatile("ldmatrix.sync.aligned.m8n8.x2.shared.b16 {%0,%1}, [%2];" \
                 : "=r"(r0), "=r"(r1) : "r"(a))
#define MMA16816(d, a, b) \
    asm volatile("mma.sync.aligned.m16n8k16.row.col.f32.bf16.bf16.f32 " \
                 "{%0,%1,%2,%3}, {%4,%5,%6,%7}, {%8,%9}, {%0,%1,%2,%3};" \
                 : "+f"((d)[0]), "+f"((d)[1]), "+f"((d)[2]), "+f"((d)[3]) \
                 : "r"((a)[0]), "r"((a)[1]), "r"((a)[2]), "r"((a)[3]), \
                   "r"((b)[0]), "r"((b)[1]))

__device__ __forceinline__ uint32_t smem_u32(const void* p) {
    uint32_t a;
    asm("{ .reg .u64 t; cvta.to.shared.u64 t, %1; cvt.u32.u64 %0, t; }" : "=r"(a) : "l"(p));
    return a;
}

__device__ __forceinline__ unsigned pack_hilo(float v) {
    __nv_bfloat16 h = __float2bfloat16(v);
    float rem = v - __bfloat162float(h);
    __nv_bfloat16 l = __float2bfloat16(rem);
    return (unsigned)__bfloat16_as_ushort(h) | ((unsigned)__bfloat16_as_ushort(l) << 16);
}

// =====================================================================================
// Prep kernels: build bf16 hi/lo split operands
// =====================================================================================
__global__ void __launch_bounds__(256) prep_wx_kernel(
    const float* __restrict__ Wz, const float* __restrict__ Wr, const float* __restrict__ Wh,
    const float* __restrict__ bz, const float* __restrict__ br, const float* __restrict__ bh)
{
    int idx = blockIdx.x * 256 + threadIdx.x;
    if (idx < NG * XPART) {
        int j = idx / XPART, k = idx - j * XPART;
        int gate = j >> 9, jj = j & 511;
        const float* W = (gate == 0) ? Wz : (gate == 1) ? Wr : Wh;
        float v = W[(size_t)jj * INDIM + k];
        __nv_bfloat16 hi = __float2bfloat16(v);
        __nv_bfloat16 lo = __float2bfloat16(v - __bfloat162float(hi));
        g_Wxh[idx] = hi; g_Wxl[idx] = lo;
    }
    if (idx < NG) {
        g_bcat[idx] = (idx < 512) ? bz[idx] : (idx < 1024) ? br[idx - 512] : bh[idx - 1024];
    }
}

__global__ void __launch_bounds__(256) prep_wb_kernel(const float* __restrict__ Wb)
{
    int idx = blockIdx.x * 256 + threadIdx.x;
    if (idx < BDIM * HDIM) {
        float v = Wb[idx];
        __nv_bfloat16 hi = __float2bfloat16(v);
        __nv_bfloat16 lo = __float2bfloat16(v - __bfloat162float(hi));
        g_Wbh[idx] = hi; g_Wbl[idx] = lo;
    }
}

// x (b, s, t, i) -> Xh/Xl[(b*SEQ+t)*768 + s*256 + i]
__global__ void __launch_bounds__(256) prep_x_kernel(const float* __restrict__ x)
{
    int idx = blockIdx.x * 256 + threadIdx.x;      // one float4
    size_t e = (size_t)idx * 4;
    int b = (int)(e / 1572864);                    // 3*2048*256
    int r = (int)(e - (size_t)b * 1572864);
    int s = r / 524288;                            // 2048*256
    int r2 = r - s * 524288;
    int t = r2 >> 8, i = r2 & 255;
    float4 v = *(const float4*)(x + e);
    size_t dst = ((size_t)b * SEQ + t) * XPART + s * 256 + i;
    __nv_bfloat16 hx = __float2bfloat16(v.x), hy = __float2bfloat16(v.y);
    __nv_bfloat16 hz = __float2bfloat16(v.z), hw = __float2bfloat16(v.w);
    *(__nv_bfloat162*)(g_Xh + dst)     = __nv_bfloat162(hx, hy);
    *(__nv_bfloat162*)(g_Xh + dst + 2) = __nv_bfloat162(hz, hw);
    *(__nv_bfloat162*)(g_Xl + dst)     = __nv_bfloat162(
        __float2bfloat16(v.x - __bfloat162float(hx)), __float2bfloat16(v.y - __bfloat162float(hy)));
    *(__nv_bfloat162*)(g_Xl + dst + 2) = __nv_bfloat162(
        __float2bfloat16(v.z - __bfloat162float(hz)), __float2bfloat16(v.w - __bfloat162float(hw)));
}

// =====================================================================================
// mma.sync bf16 GEMM (stages 1 & 3) — unchanged from round 3
// =====================================================================================
#define SMSTRIDE 40

__global__ void __launch_bounds__(256) gemm_mma_kernel(
    const __nv_bfloat16* __restrict__ Ah, const __nv_bfloat16* __restrict__ Al, int lda,
    const __nv_bfloat16* __restrict__ Bh, const __nv_bfloat16* __restrict__ Bl, int ldb,
    const float* __restrict__ bias, float* __restrict__ C, int ldc, int K32)
{
    __shared__ __align__(16) __nv_bfloat16 As[128][SMSTRIDE];
    __shared__ __align__(16) __nv_bfloat16 Bs[128][SMSTRIDE];

    const int tid  = threadIdx.x;
    const int wid  = tid >> 5;
    const int lane = tid & 31;
    const int n0   = blockIdx.x * 128;
    const int m0   = blockIdx.y * 128;
    const int m0w  = (wid & 3) * 32;
    const int n0w  = (wid >> 2) * 64;

    const int gr0 = (tid * 2) >> 2,     gc0 = ((tid * 2) & 3) * 8;
    const int gr1 = (tid * 2 + 1) >> 2, gc1 = ((tid * 2 + 1) & 3) * 8;

    uint32_t sA = smem_u32(&As[0][0]);
    uint32_t sB = smem_u32(&Bs[0][0]);
    const int a_row = m0w + (lane & 7) + ((lane >> 3) & 1) * 8;
    const int a_kof = ((lane >> 4) & 1) * 8;
    const int b_row = n0w + (lane & 7) + ((lane >> 4) & 1) * 8;
    const int b_kof = ((lane >> 3) & 1) * 8;

    float acc[2][8][4];
    #pragma unroll
    for (int i = 0; i < 2; i++)
        #pragma unroll
        for (int j = 0; j < 8; j++)
            #pragma unroll
            for (int q = 0; q < 4; q++) acc[i][j][q] = 0.f;

    const int NC = 3 * K32;
    uint4 pa0, pa1, pb0, pb1;
    pa0 = *(const uint4*)(Ah + (size_t)(m0 + gr0) * lda + gc0);
    pa1 = *(const uint4*)(Ah + (size_t)(m0 + gr1) * lda + gc1);
    pb0 = *(const uint4*)(Bh + (size_t)(n0 + gr0) * ldb + gc0);
    pb1 = *(const uint4*)(Bh + (size_t)(n0 + gr1) * ldb + gc1);

    #pragma unroll 1
    for (int c = 0; c < NC; c++) {
        *(uint4*)&As[gr0][gc0] = pa0;
        *(uint4*)&As[gr1][gc1] = pa1;
        *(uint4*)&Bs[gr0][gc0] = pb0;
        *(uint4*)&Bs[gr1][gc1] = pb1;
        __syncthreads();

        if (c + 1 < NC) {
            const int cn = c + 1;
            const int ph = cn / K32;
            const int kk = (cn - ph * K32) * 32;
            const __nv_bfloat16* Asrc = (ph < 2) ? Ah : Al;
            const __nv_bfloat16* Bsrc = (ph == 1) ? Bl : Bh;
            pa0 = *(const uint4*)(Asrc + (size_t)(m0 + gr0) * lda + kk + gc0);
            pa1 = *(const uint4*)(Asrc + (size_t)(m0 + gr1) * lda + kk + gc1);
            pb0 = *(const uint4*)(Bsrc + (size_t)(n0 + gr0) * ldb + kk + gc0);
            pb1 = *(const uint4*)(Bsrc + (size_t)(n0 + gr1) * ldb + kk + gc1);
        }

        #pragma unroll
        for (int ks = 0; ks < 2; ks++) {
            uint32_t af[2][4];
            #pragma unroll
            for (int mb = 0; mb < 2; mb++) {
                uint32_t ad = sA + (uint32_t)((a_row + mb * 16) * (SMSTRIDE * 2)
                                              + (ks * 16 + a_kof) * 2);
                LDM_X4(af[mb][0], af[mb][1], af[mb][2], af[mb][3], ad);
            }
            uint32_t bf[8][2];
            #pragma unroll
            for (int q = 0; q < 4; q++) {
                uint32_t bd = sB + (uint32_t)((b_row + q * 16) * (SMSTRIDE * 2)
                                              + (ks * 16 + b_kof) * 2);
                LDM_X4(bf[2 * q][0], bf[2 * q][1], bf[2 * q + 1][0], bf[2 * q + 1][1], bd);
            }
            #pragma unroll
            for (int mb = 0; mb < 2; mb++)
                #pragma unroll
                for (int nb = 0; nb < 8; nb++)
                    MMA16816(acc[mb][nb], af[mb], bf[nb]);
        }
        __syncthreads();
    }

    const int g   = lane >> 2;
    const int tig = lane & 3;
    #pragma unroll
    for (int mb = 0; mb < 2; mb++) {
        #pragma unroll
        for (int nb = 0; nb < 8; nb++) {
            int col = n0 + n0w + nb * 8 + tig * 2;
            float b0 = bias[col], b1 = bias[col + 1];
            int r0 = m0 + m0w + mb * 16 + g;
            *(float2*)(C + (size_t)r0 * ldc + col) =
                make_float2(acc[mb][nb][0] + b0, acc[mb][nb][1] + b1);
            *(float2*)(C + (size_t)(r0 + 8) * ldc + col) =
                make_float2(acc[mb][nb][2] + b0, acc[mb][nb][3] + b1);
        }
    }
}

// =====================================================================================
// Stage 2: persistent TENSOR-CORE recurrence.
//   128 CTAs = 8 bslabs (8 batches) x 16 jslabs (32 dims). 256 threads (8 warps).
//   Weights (hi+lo bf16, stride 520) resident in smem. h fp32 kept in smem per CTA.
//   Per step: phase A (z|r, N64) -> combine -> barrier -> phase B (h~, N32) -> combine
//   -> barrier.  MMA M16 with rows 8..15 aliased to a zero row.
//   Grid barrier: monotonic red.release counter + ld.acquire spin.
// =====================================================================================
#define WROW   1040                 // weight/A smem row stride in bytes (520 bf16)
#define OFF_WZRH 0
#define OFF_WZRL (OFF_WZRH + 64*WROW)
#define OFF_WHH  (OFF_WZRL + 64*WROW)
#define OFF_WHL  (OFF_WHH  + 32*WROW)
#define OFF_AHI  (OFF_WHL  + 32*WROW)
#define OFF_ALO  (OFF_AHI  + 8*WROW)
#define OFF_Z    (OFF_ALO  + 8*WROW)
#define OFF_CRED (OFF_Z    + WROW)
#define OFF_H32  (OFF_CRED + 2*8*66*4)
#define OFF_ZB   (OFF_H32  + 1024)
#define SMEM2_TOTAL (OFF_ZB + 1024)

#define CRED(p, h, r, n) p[((h) * 8 + (r)) * 66 + (n)]

__device__ __forceinline__ void gbar(unsigned* cnt, unsigned target) {
    __syncthreads();
    if (threadIdx.x == 0) {
        asm volatile("red.release.gpu.global.add.u32 [%0], %1;" :: "l"(cnt), "r"(1u));
        unsigned c;
        do {
            asm volatile("ld.acquire.gpu.global.u32 %0, [%1];" : "=r"(c) : "l"(cnt));
        } while ((int)(c - target) < 0);
    }
    __syncthreads();
}

__global__ void __launch_bounds__(256, 1) recurrent_tc_kernel(
    const float* __restrict__ Wz, const float* __restrict__ Wr, const float* __restrict__ Wh,
    float* __restrict__ out)
{
    extern __shared__ char smem[];
    const uint32_t sbase = smem_u32(smem);
    float* credf = (float*)(smem + OFF_CRED);
    float* h32   = (float*)(smem + OFF_H32);
    float* zbuf  = (float*)(smem + OFF_ZB);

    const int tid  = threadIdx.x;
    const int wid  = tid >> 5;
    const int lane = tid & 31;
    const int blk  = blockIdx.x;
    const int b0   = (blk >> 4) * 8;
    const int j0   = (blk & 15) * 32;

    // ---- load + split weights into smem (one-time) ----
    for (int e = tid; e < 64 * 512; e += 256) {
        int row = e >> 9, k = e & 511;
        const float* W = (row < 32) ? Wz : Wr;
        float v = W[(size_t)(j0 + (row & 31)) * INDIM + XPART + k];
        __nv_bfloat16 hi = __float2bfloat16(v);
        __nv_bfloat16 lo = __float2bfloat16(v - __bfloat162float(hi));
        *(__nv_bfloat16*)(smem + OFF_WZRH + row * WROW + k * 2) = hi;
        *(__nv_bfloat16*)(smem + OFF_WZRL + row * WROW + k * 2) = lo;
    }
    for (int e = tid; e < 32 * 512; e += 256) {
        int row = e >> 9, k = e & 511;
        float v = Wh[(size_t)(j0 + row) * INDIM + XPART + k];
        __nv_bfloat16 hi = __float2bfloat16(v);
        __nv_bfloat16 lo = __float2bfloat16(v - __bfloat162float(hi));
        *(__nv_bfloat16*)(smem + OFF_WHH + row * WROW + k * 2) = hi;
        *(__nv_bfloat16*)(smem + OFF_WHL + row * WROW + k * 2) = lo;
    }
    for (int i = tid; i < 260; i += 256) *(uint32_t*)(smem + OFF_Z + i * 4) = 0;
    h32[tid] = 0.f;
    // zero my slab of g_hpk (initial h = 0)
    g_hpk[(b0 + (tid >> 5)) * HDIM + j0 + (tid & 31)] = 0u;

    unsigned tgt = NBLK2;
    gbar(&g_cnt, tgt); tgt += NBLK2;

    // ---- per-warp fragment address bases ----
    const int kh = wid >> 2;                 // K half: 0 -> k[0,256), 1 -> k[256,512)
    const int khB = kh * 512;                // byte offset of K half
    const int arow = lane & 7;
    const int azero = (lane >> 3) & 1;
    const uint32_t akof = (uint32_t)(((lane >> 4) & 1) * 16);
    const uint32_t aAhi = sbase + (azero ? OFF_Z : OFF_AHI + arow * WROW) + akof + khB;
    const uint32_t aAlo = sbase + (azero ? OFF_Z : OFF_ALO + arow * WROW) + akof + khB;

    const int nsA = wid & 3;                 // phase A N16 slice
    const int browA = nsA * 16 + (lane & 7) + ((lane >> 4) & 1) * 8;
    const uint32_t bkofA = (uint32_t)(((lane >> 3) & 1) * 16);
    const uint32_t bZH = sbase + OFF_WZRH + browA * WROW + bkofA + khB;
    const uint32_t bZL = sbase + OFF_WZRL + browA * WROW + bkofA + khB;

    const int browB = (wid & 3) * 8 + (lane & 7);   // phase B N8 slice
    const uint32_t bkofB = (uint32_t)(((lane >> 3) & 1) * 16);
    const uint32_t bWH = sbase + OFF_WHH + browB * WROW + bkofB + khB;
    const uint32_t bWL = sbase + OFF_WHL + browB * WROW + bkofB + khB;

    // combine mappings + running XG pointers
    const int cbA = tid >> 6;                // combine A: batches cbA and cbA+4
    const int cnA = tid & 63;                // 0..31 -> z, 32..63 -> r
    const int colA = (cnA < 32) ? (j0 + cnA) : (512 + j0 + (cnA - 32));
    const float* pxA0 = g_XG + (size_t)(b0 + cbA)     * SEQ * NG + colA;
    const float* pxA1 = g_XG + (size_t)(b0 + cbA + 4) * SEQ * NG + colA;
    const int cbB = tid >> 5, cjB = tid & 31;
    const float* pxB = g_XG + (size_t)(b0 + cbB) * SEQ * NG + 1024 + j0 + cjB;

    const int crow = lane >> 2;              // C frag row (0..7)
    const int ccol = (lane & 3) * 2;

    unsigned* hpk_my  = g_hpk  + (size_t)b0 * HDIM;
    unsigned* rhpk_my = g_rhpk + (size_t)b0 * HDIM;

    #pragma unroll 1
    for (int t = 0; t < SEQ; t++) {
        // prefetch XG for this step
        float xa0 = *pxA0, xa1 = *pxA1, xb = *pxB;
        pxA0 += NG; pxA1 += NG; pxB += NG;

        // ---- load h (packed) -> Ahi/Alo ----
        #pragma unroll
        for (int q = 0; q < 8; q++) {
            uint2 w = *(const uint2*)(hpk_my + q * 512 + tid * 2);
            *(uint32_t*)(smem + OFF_AHI + q * WROW + tid * 4) = __byte_perm(w.x, w.y, 0x5410);
            *(uint32_t*)(smem + OFF_ALO + q * WROW + tid * 4) = __byte_perm(w.x, w.y, 0x7632);
        }
        __syncthreads();

        // ---- phase A mma: z|r preacts, N64, K augmented 3x256 per half ----
        {
            float acc0[4] = {0.f, 0.f, 0.f, 0.f};
            float acc1[4] = {0.f, 0.f, 0.f, 0.f};
            #pragma unroll 1
            for (int p = 0; p < 3; p++) {
                uint32_t ab = (p < 2) ? aAhi : aAlo;
                uint32_t bb = (p == 1) ? bZL : bZH;
                #pragma unroll
                for (int k16 = 0; k16 < 16; k16++) {
                    uint32_t off = (uint32_t)(k16 * 32);
                    uint32_t a[4], b[4];
                    LDM_X4(a[0], a[1], a[2], a[3], ab + off);
                    LDM_X4(b[0], b[1], b[2], b[3], bb + off);
                    MMA16816(acc0, a, b);
                    MMA16816(acc1, a, b + 2);
                }
            }
            // stage rows 0..7 only (rows 8..15 are zero-A)
            int n0w = nsA * 16;
            *(float2*)&CRED(credf, kh, crow, n0w + ccol)     = make_float2(acc0[0], acc0[1]);
            *(float2*)&CRED(credf, kh, crow, n0w + 8 + ccol) = make_float2(acc1[0], acc1[1]);
        }
        __syncthreads();

        // ---- combine A: sigmoid, publish z (smem) and r*h (global packed) ----
        {
            #pragma unroll
            for (int it = 0; it < 2; it++) {
                int b = cbA + it * 4;
                float s = CRED(credf, 0, b, cnA) + CRED(credf, 1, b, cnA)
                        + (it == 0 ? xa0 : xa1);
                float sig = 1.f / (1.f + __expf(-s));
                if (cnA < 32) {
                    zbuf[b * 32 + cnA] = sig;
                } else {
                    int jl = cnA - 32;
                    float rh = sig * h32[b * 32 + jl];
                    rhpk_my[b * 512 + j0 + jl] = pack_hilo(rh);
                }
            }
        }
        gbar(&g_cnt, tgt); tgt += NBLK2;

        // ---- load rh (packed) -> Ahi/Alo ----
        #pragma unroll
        for (int q = 0; q < 8; q++) {
            uint2 w = *(const uint2*)(rhpk_my + q * 512 + tid * 2);
            *(uint32_t*)(smem + OFF_AHI + q * WROW + tid * 4) = __byte_perm(w.x, w.y, 0x5410);
            *(uint32_t*)(smem + OFF_ALO + q * WROW + tid * 4) = __byte_perm(w.x, w.y, 0x7632);
        }
        __syncthreads();

        // ---- phase B mma: h~ preacts, N32 ----
        {
            float acc[4] = {0.f, 0.f, 0.f, 0.f};
            #pragma unroll 1
            for (int p = 0; p < 3; p++) {
                uint32_t ab = (p < 2) ? aAhi : aAlo;
                uint32_t bb = (p == 1) ? bWL : bWH;
                #pragma unroll
                for (int k16 = 0; k16 < 16; k16++) {
                    uint32_t off = (uint32_t)(k16 * 32);
                    uint32_t a[4], b[2];
                    LDM_X4(a[0], a[1], a[2], a[3], ab + off);
                    LDM_X2(b[0], b[1], bb + off);
                    MMA16816(acc, a, b);
                }
            }
            int n0w = (wid & 3) * 8;
            *(float2*)&CRED(credf, kh, crow, n0w + ccol) = make_float2(acc[0], acc[1]);
        }
        __syncthreads();

        // ---- combine B: tanh, blend, publish h (global packed + stage-3 bf16 + fp32 smem) ----
        {
            float s = CRED(credf, 0, cbB, cjB) + CRED(credf, 1, cbB, cjB) + xb;
            float ht = tanhf(s);
            float hp = h32[tid];
            float z  = zbuf[tid];
            float hn = hp + z * (ht - hp);
            h32[tid] = hn;
            __nv_bfloat16 hi = __float2bfloat16(hn);
            __nv_bfloat16 lo = __float2bfloat16(hn - __bfloat162float(hi));
            hpk_my[cbB * 512 + j0 + cjB] =
                (unsigned)__bfloat16_as_ushort(hi) | ((unsigned)__bfloat16_as_ushort(lo) << 16);
            size_t hrow = ((size_t)(b0 + cbB) * SEQ + t) * HDIM + j0 + cjB;
            g_Hh[hrow] = hi;
            g_Hl[hrow] = lo;
            if (t == SEQ - 1)
                out[(size_t)BATCH * SEQ * BDIM + (b0 + cbB) * HDIM + j0 + cjB] = hn;
        }
        gbar(&g_cnt, tgt); tgt += NBLK2;
    }
}

// =====================================================================================
extern "C" void kernel_launch(void* const* d_in, const int* in_sizes, int n_in,
                              void* d_out, int out_size)
{
    (void)in_sizes; (void)n_in; (void)out_size;
    const float* x  = (const float*)d_in[0];
    const float* Wz = (const float*)d_in[1];
    const float* bz = (const float*)d_in[2];
    const float* Wr = (const float*)d_in[3];
    const float* br = (const float*)d_in[4];
    const float* Wh = (const float*)d_in[5];
    const float* bh = (const float*)d_in[6];
    const float* Wb = (const float*)d_in[7];
    const float* bb = (const float*)d_in[8];
    float* out = (float*)d_out;

    cudaFuncSetAttribute(recurrent_tc_kernel,
                         cudaFuncAttributeMaxDynamicSharedMemorySize, SMEM2_TOTAL);

    __nv_bfloat16 *Xh, *Xl, *Wxh, *Wxl, *Hh, *Hl, *Wbh, *Wbl;
    float *XG, *bcat;
    unsigned* cntp;
    cudaGetSymbolAddress((void**)&Xh,  g_Xh);
    cudaGetSymbolAddress((void**)&Xl,  g_Xl);
    cudaGetSymbolAddress((void**)&Wxh, g_Wxh);
    cudaGetSymbolAddress((void**)&Wxl, g_Wxl);
    cudaGetSymbolAddress((void**)&Hh,  g_Hh);
    cudaGetSymbolAddress((void**)&Hl,  g_Hl);
    cudaGetSymbolAddress((void**)&Wbh, g_Wbh);
    cudaGetSymbolAddress((void**)&Wbl, g_Wbl);
    cudaGetSymbolAddress((void**)&XG,  g_XG);
    cudaGetSymbolAddress((void**)&bcat, g_bcat);
    cudaGetSymbolAddress((void**)&cntp, g_cnt);

    // Prep: bf16 hi/lo splits
    prep_wx_kernel<<<(NG * XPART + 255) / 256, 256>>>(Wz, Wr, Wh, bz, br, bh);
    prep_wb_kernel<<<(BDIM * HDIM + 255) / 256, 256>>>(Wb);
    prep_x_kernel<<<(M_TOTAL * XPART / 4) / 256, 256>>>(x);

    // Stage 1: XG = xcat @ Wx^T + bcat
    gemm_mma_kernel<<<dim3(NG / 128, M_TOTAL / 128), 256>>>(
        Xh, Xl, XPART, Wxh, Wxl, XPART, bcat, XG, NG, XPART / 32);

    // Stage 2: persistent tensor-core recurrence (writes g_Hh/g_Hl + h_fin tail)
    cudaMemsetAsync(cntp, 0, sizeof(unsigned));
    recurrent_tc_kernel<<<NBLK2, 256, SMEM2_TOTAL>>>(Wz, Wr, Wh, out);

    // Stage 3: out = H @ Wb^T + bb
    gemm_mma_kernel<<<dim3(BDIM / 128, M_TOTAL / 128), 256>>>(
        Hh, Hl, HDIM, Wbh, Wbl, HDIM, bb, out, BDIM, HDIM / 32);
}

// round 6
// speedup vs baseline: 1.8205x; 1.1375x over previous
#include <cuda_runtime.h>
#include <cuda_bf16.h>
#include <cstdint>
#include <cstddef>

// Problem constants
#define BATCH   64
#define SEQ     2048
#define IDIM    256
#define HDIM    512
#define BDIM    256
#define INDIM   1280     // 3*IDIM + HDIM
#define XPART   768      // 3*IDIM
#define M_TOTAL (BATCH * SEQ)   // 131072
#define NG      1536     // 3 gates * HDIM

#define NBLK2   128      // persistent recurrent grid (1 CTA/SM -> co-resident)

// -------------------- scratch (static __device__, allocation-free) --------------------
__device__ float g_XG[(size_t)M_TOTAL * NG];        // [b*SEQ+t][1536]: xz | xr | xh pre-acts
__device__ unsigned g_cnt;                          // monotonic grid-barrier counter

// packed bf16 hi|lo exchange buffers (u32 = hi | lo<<16)
__device__ unsigned g_hpk [BATCH * HDIM];           // h_t
__device__ unsigned g_rhpk[BATCH * HDIM];           // r*h

// bf16 split operands
__device__ __nv_bfloat16 g_Xh[(size_t)M_TOTAL * XPART];   // x concat hi, [b*SEQ+t][768]
__device__ __nv_bfloat16 g_Xl[(size_t)M_TOTAL * XPART];
__device__ __nv_bfloat16 g_Wxh[(size_t)NG * XPART];       // [1536][768] x-part of Wz|Wr|Wh
__device__ __nv_bfloat16 g_Wxl[(size_t)NG * XPART];
__device__ __nv_bfloat16 g_Hh[(size_t)M_TOTAL * HDIM];    // hidden states, [b*SEQ+t][512]
__device__ __nv_bfloat16 g_Hl[(size_t)M_TOTAL * HDIM];
__device__ __nv_bfloat16 g_Wbh[(size_t)BDIM * HDIM];
__device__ __nv_bfloat16 g_Wbl[(size_t)BDIM * HDIM];
__device__ float g_bcat[NG];

// =====================================================================================
// MMA / ldmatrix / cp.async macros (portable sm_80+ PTX)
// =====================================================================================
#define LDM_X4(r0, r1, r2, r3, a) \
    asm volatile("ldmatrix.sync.aligned.m8n8.x4.shared.b16 {%0,%1,%2,%3}, [%4];" \
                 : "=r"(r0), "=r"(r1), "=r"(r2), "=r"(r3) : "r"(a))
#define LDM_X2(r0, r1, a) \
    asm volatile("ldmatrix.sync.aligned.m8n8.x2.shared.b16 {%0,%1}, [%2];" \
                 : "=r"(r0), "=r"(r1) : "r"(a))
#define MMA16816(d, a, b) \
    asm volatile("mma.sync.aligned.m16n8k16.row.col.f32.bf16.bf16.f32 " \
                 "{%0,%1,%2,%3}, {%4,%5,%6,%7}, {%8,%9}, {%0,%1,%2,%3};" \
                 : "+f"((d)[0]), "+f"((d)[1]), "+f"((d)[2]), "+f"((d)[3]) \
                 : "r"((a)[0]), "r"((a)[1]), "r"((a)[2]), "r"((a)[3]), \
                   "r"((b)[0]), "r"((b)[1]))
#define CP_ASYNC16(dst, src) \
    asm volatile("cp.async.cg.shared.global [%0], [%1], 16;" :: "r"(dst), "l"(src))
#define CP_COMMIT() asm volatile("cp.async.commit_group;" ::: "memory")
#define CP_WAIT1()  asm volatile("cp.async.wait_group 1;" ::: "memory")
#define CP_WAIT0()  asm volatile("cp.async.wait_group 0;" ::: "memory")

__device__ __forceinline__ uint32_t smem_u32(const void* p) {
    uint32_t a;
    asm("{ .reg .u64 t; cvta.to.shared.u64 t, %1; cvt.u32.u64 %0, t; }" : "=r"(a) : "l"(p));
    return a;
}

// =====================================================================================
// Prep kernels: build bf16 hi/lo split operands
// =====================================================================================
__global__ void __launch_bounds__(256) prep_wx_kernel(
    const float* __restrict__ Wz, const float* __restrict__ Wr, const float* __restrict__ Wh,
    const float* __restrict__ bz, const float* __restrict__ br, const float* __restrict__ bh)
{
    int idx = blockIdx.x * 256 + threadIdx.x;
    if (idx < NG * XPART) {
        int j = idx / XPART, k = idx - j * XPART;
        int gate = j >> 9, jj = j & 511;
        const float* W = (gate == 0) ? Wz : (gate == 1) ? Wr : Wh;
        float v = W[(size_t)jj * INDIM + k];
        __nv_bfloat16 hi = __float2bfloat16(v);
        __nv_bfloat16 lo = __float2bfloat16(v - __bfloat162float(hi));
        g_Wxh[idx] = hi; g_Wxl[idx] = lo;
    }
    if (idx < NG) {
        g_bcat[idx] = (idx < 512) ? bz[idx] : (idx < 1024) ? br[idx - 512] : bh[idx - 1024];
    }
}

__global__ void __launch_bounds__(256) prep_wb_kernel(const float* __restrict__ Wb)
{
    int idx = blockIdx.x * 256 + threadIdx.x;
    if (idx < BDIM * HDIM) {
        float v = Wb[idx];
        __nv_bfloat16 hi = __float2bfloat16(v);
        __nv_bfloat16 lo = __float2bfloat16(v - __bfloat162float(hi));
        g_Wbh[idx] = hi; g_Wbl[idx] = lo;
    }
}

// x (b, s, t, i) -> Xh/Xl[(b*SEQ+t)*768 + s*256 + i]
__global__ void __launch_bounds__(256) prep_x_kernel(const float* __restrict__ x)
{
    int idx = blockIdx.x * 256 + threadIdx.x;      // one float4
    size_t e = (size_t)idx * 4;
    int b = (int)(e / 1572864);                    // 3*2048*256
    int r = (int)(e - (size_t)b * 1572864);
    int s = r / 524288;                            // 2048*256
    int r2 = r - s * 524288;
    int t = r2 >> 8, i = r2 & 255;
    float4 v = *(const float4*)(x + e);
    size_t dst = ((size_t)b * SEQ + t) * XPART + s * 256 + i;
    __nv_bfloat16 hx = __float2bfloat16(v.x), hy = __float2bfloat16(v.y);
    __nv_bfloat16 hz = __float2bfloat16(v.z), hw = __float2bfloat16(v.w);
    *(__nv_bfloat162*)(g_Xh + dst)     = __nv_bfloat162(hx, hy);
    *(__nv_bfloat162*)(g_Xh + dst + 2) = __nv_bfloat162(hz, hw);
    *(__nv_bfloat162*)(g_Xl + dst)     = __nv_bfloat162(
        __float2bfloat16(v.x - __bfloat162float(hx)), __float2bfloat16(v.y - __bfloat162float(hy)));
    *(__nv_bfloat162*)(g_Xl + dst + 2) = __nv_bfloat162(
        __float2bfloat16(v.z - __bfloat162float(hz)), __float2bfloat16(v.w - __bfloat162float(hw)));
}

// =====================================================================================
// cp.async double-buffered mma.sync GEMM (stages 1 & 3).
//   C[m][n] = bias[n] + sum_k A[m][k]*B[n][k],  augmented K: AhBh | AhBl | AlBh
//   CTA tile 128M x 256N x BK32, 8 warps (2M x 4N), warp tile 64x64.
// =====================================================================================
#define GSTRIDE 80                      // smem row stride bytes (32 bf16 data + 8 pad)
#define G_ABYTES (128 * GSTRIDE)        // 10240
#define G_BBYTES (256 * GSTRIDE)        // 20480
#define G_STAGE  (G_ABYTES + G_BBYTES)  // 30720
#define GEMM_SMEM (2 * G_STAGE)         // 61440

__global__ void __launch_bounds__(256) gemm_mma_kernel(
    const __nv_bfloat16* __restrict__ Ah, const __nv_bfloat16* __restrict__ Al, int lda,
    const __nv_bfloat16* __restrict__ Bh, const __nv_bfloat16* __restrict__ Bl, int ldb,
    const float* __restrict__ bias, float* __restrict__ C, int ldc, int K32)
{
    extern __shared__ char gsm[];
    const uint32_t sbase = smem_u32(gsm);

    const int tid  = threadIdx.x;
    const int wid  = tid >> 5;
    const int lane = tid & 31;
    const int n0   = blockIdx.x * 256;
    const int m0   = blockIdx.y * 128;
    const int m0w  = (wid & 1) * 64;
    const int n0w  = (wid >> 1) * 64;

    const int NC = 3 * K32;

    // ldmatrix per-lane address components (byte offsets within a stage)
    const uint32_t a_base = (uint32_t)(((lane & 7) + ((lane >> 3) & 1) * 8) * GSTRIDE
                                       + ((lane >> 4) & 1) * 16);
    const uint32_t b_base = (uint32_t)(((lane & 7) + ((lane >> 4) & 1) * 8) * GSTRIDE
                                       + ((lane >> 3) & 1) * 16);

    float acc[4][8][4];
    #pragma unroll
    for (int i = 0; i < 4; i++)
        #pragma unroll
        for (int j = 0; j < 8; j++)
            #pragma unroll
            for (int q = 0; q < 4; q++) acc[i][j][q] = 0.f;

    // ---- async tile loader: chunk c -> stage buf ----
    auto issue = [&](int c) {
        const int ph = c / K32;
        const int kk = (c - ph * K32) * 32;
        const __nv_bfloat16* Asrc = (ph < 2) ? Ah : Al;
        const __nv_bfloat16* Bsrc = (ph == 1) ? Bl : Bh;
        const uint32_t sb = sbase + (uint32_t)((c & 1) * G_STAGE);
        #pragma unroll
        for (int i = 0; i < 2; i++) {                       // A: 512 16B units
            int u = tid + i * 256;
            int row = u >> 2, c16 = u & 3;
            CP_ASYNC16(sb + row * GSTRIDE + c16 * 16,
                       Asrc + (size_t)(m0 + row) * lda + kk + c16 * 8);
        }
        #pragma unroll
        for (int i = 0; i < 4; i++) {                       // B: 1024 16B units
            int u = tid + i * 256;
            int row = u >> 2, c16 = u & 3;
            CP_ASYNC16(sb + G_ABYTES + row * GSTRIDE + c16 * 16,
                       Bsrc + (size_t)(n0 + row) * ldb + kk + c16 * 8);
        }
        CP_COMMIT();
    };

    issue(0);

    #pragma unroll 1
    for (int c = 0; c < NC; c++) {
        if (c + 1 < NC) { issue(c + 1); CP_WAIT1(); } else { CP_WAIT0(); }
        __syncthreads();

        const uint32_t sb = sbase + (uint32_t)((c & 1) * G_STAGE);
        const uint32_t sA = sb + (uint32_t)(m0w * GSTRIDE) + a_base;
        const uint32_t sB = sb + G_ABYTES + (uint32_t)(n0w * GSTRIDE) + b_base;

        #pragma unroll
        for (int ks = 0; ks < 2; ks++) {
            uint32_t af[4][4];
            #pragma unroll
            for (int mb = 0; mb < 4; mb++)
                LDM_X4(af[mb][0], af[mb][1], af[mb][2], af[mb][3],
                       sA + (uint32_t)(mb * 16 * GSTRIDE + ks * 32));
            uint32_t bf[8][2];
            #pragma unroll
            for (int q = 0; q < 4; q++)
                LDM_X4(bf[2 * q][0], bf[2 * q][1], bf[2 * q + 1][0], bf[2 * q + 1][1],
                       sB + (uint32_t)(q * 16 * GSTRIDE + ks * 32));
            #pragma unroll
            for (int mb = 0; mb < 4; mb++)
                #pragma unroll
                for (int nb = 0; nb < 8; nb++)
                    MMA16816(acc[mb][nb], af[mb], bf[nb]);
        }
        __syncthreads();
    }

    // epilogue
    const int g   = lane >> 2;
    const int tig = lane & 3;
    #pragma unroll
    for (int mb = 0; mb < 4; mb++) {
        #pragma unroll
        for (int nb = 0; nb < 8; nb++) {
            int col = n0 + n0w + nb * 8 + tig * 2;
            float b0 = bias[col], b1 = bias[col + 1];
            int r0 = m0 + m0w + mb * 16 + g;
            *(float2*)(C + (size_t)r0 * ldc + col) =
                make_float2(acc[mb][nb][0] + b0, acc[mb][nb][1] + b1);
            *(float2*)(C + (size_t)(r0 + 8) * ldc + col) =
                make_float2(acc[mb][nb][2] + b0, acc[mb][nb][3] + b1);
        }
    }
}

// =====================================================================================
// Stage 2: persistent TENSOR-CORE recurrence, M-packed hi/lo (rows 0-7 hi, 8-15 lo).
//   Two B passes (W_hi, W_lo) give the full 4-term split product; combine adds
//   C rows m and m+8. 128 CTAs = 8 bslabs x 16 jslabs, 8 warps.
// =====================================================================================
#define WROW   1040                 // weight/A smem row stride in bytes (520 bf16)
#define OFF_WZRH 0
#define OFF_WZRL (OFF_WZRH + 64*WROW)
#define OFF_WHH  (OFF_WZRL + 64*WROW)
#define OFF_WHL  (OFF_WHH  + 32*WROW)
#define OFF_AHI  (OFF_WHL  + 32*WROW)
#define OFF_ALO  (OFF_AHI  + 8*WROW)
#define OFF_CRED (OFF_ALO  + 8*WROW)
#define OFF_H32  (OFF_CRED + 2*8*66*4)
#define OFF_ZB   (OFF_H32  + 1024)
#define SMEM2_TOTAL (OFF_ZB + 1024)

#define CRED(p, h, r, n) p[((h) * 8 + (r)) * 66 + (n)]

__device__ __forceinline__ void gbar(unsigned* cnt, unsigned target) {
    __syncthreads();
    if (threadIdx.x == 0) {
        asm volatile("red.release.gpu.global.add.u32 [%0], %1;" :: "l"(cnt), "r"(1u));
        unsigned c;
        do {
            asm volatile("ld.acquire.gpu.global.u32 %0, [%1];" : "=r"(c) : "l"(cnt));
        } while ((int)(c - target) < 0);
    }
    __syncthreads();
}

__global__ void __launch_bounds__(256, 1) recurrent_tc_kernel(
    const float* __restrict__ Wz, const float* __restrict__ Wr, const float* __restrict__ Wh,
    float* __restrict__ out)
{
    extern __shared__ char smem[];
    const uint32_t sbase = smem_u32(smem);
    float* credf = (float*)(smem + OFF_CRED);
    float* h32   = (float*)(smem + OFF_H32);
    float* zbuf  = (float*)(smem + OFF_ZB);

    const int tid  = threadIdx.x;
    const int wid  = tid >> 5;
    const int lane = tid & 31;
    const int blk  = blockIdx.x;
    const int b0   = (blk >> 4) * 8;
    const int j0   = (blk & 15) * 32;

    // ---- load + split weights into smem (one-time) ----
    for (int e = tid; e < 64 * 512; e += 256) {
        int row = e >> 9, k = e & 511;
        const float* W = (row < 32) ? Wz : Wr;
        float v = W[(size_t)(j0 + (row & 31)) * INDIM + XPART + k];
        __nv_bfloat16 hi = __float2bfloat16(v);
        __nv_bfloat16 lo = __float2bfloat16(v - __bfloat162float(hi));
        *(__nv_bfloat16*)(smem + OFF_WZRH + row * WROW + k * 2) = hi;
        *(__nv_bfloat16*)(smem + OFF_WZRL + row * WROW + k * 2) = lo;
    }
    for (int e = tid; e < 32 * 512; e += 256) {
        int row = e >> 9, k = e & 511;
        float v = Wh[(size_t)(j0 + row) * INDIM + XPART + k];
        __nv_bfloat16 hi = __float2bfloat16(v);
        __nv_bfloat16 lo = __float2bfloat16(v - __bfloat162float(hi));
        *(__nv_bfloat16*)(smem + OFF_WHH + row * WROW + k * 2) = hi;
        *(__nv_bfloat16*)(smem + OFF_WHL + row * WROW + k * 2) = lo;
    }
    h32[tid] = 0.f;
    g_hpk[(b0 + (tid >> 5)) * HDIM + j0 + (tid & 31)] = 0u;

    unsigned tgt = NBLK2;
    gbar(&g_cnt, tgt); tgt += NBLK2;

    // ---- per-warp fragment address bases ----
    const int kh  = wid >> 2;                // K half: 0 -> k[0,256), 1 -> k[256,512)
    const int khB = kh * 512;                // byte offset of K half
    const int arow  = lane & 7;
    const int isLo  = (lane >> 3) & 1;       // lanes 8-15 / 24-31 -> lo rows
    const uint32_t akof = (uint32_t)(((lane >> 4) & 1) * 16);
    const uint32_t aA = sbase + (isLo ? OFF_ALO : OFF_AHI) + arow * WROW + akof + khB;

    const int nsA = wid & 3;                 // phase A N16 slice
    const int browA = nsA * 16 + (lane & 7) + ((lane >> 4) & 1) * 8;
    const uint32_t bkofA = (uint32_t)(((lane >> 3) & 1) * 16);
    const uint32_t bZH = sbase + OFF_WZRH + browA * WROW + bkofA + khB;
    const uint32_t bZL = sbase + OFF_WZRL + browA * WROW + bkofA + khB;

    const int browB = (wid & 3) * 8 + (lane & 7);   // phase B N8 slice
    const uint32_t bkofB = (uint32_t)(((lane >> 3) & 1) * 16);
    const uint32_t bWH = sbase + OFF_WHH + browB * WROW + bkofB + khB;
    const uint32_t bWL = sbase + OFF_WHL + browB * WROW + bkofB + khB;

    // combine mappings + running XG pointers
    const int cbA = tid >> 6;                // combine A: batches cbA and cbA+4
    const int cnA = tid & 63;                // 0..31 -> z, 32..63 -> r
    const int colA = (cnA < 32) ? (j0 + cnA) : (512 + j0 + (cnA - 32));
    const float* pxA0 = g_XG + (size_t)(b0 + cbA)     * SEQ * NG + colA;
    const float* pxA1 = g_XG + (size_t)(b0 + cbA + 4) * SEQ * NG + colA;
    const int cbB = tid >> 5, cjB = tid & 31;
    const float* pxB = g_XG + (size_t)(b0 + cbB) * SEQ * NG + 1024 + j0 + cjB;

    const int crow = lane >> 2;              // C frag row (0..7)
    const int ccol = (lane & 3) * 2;

    unsigned* hpk_my  = g_hpk  + (size_t)b0 * HDIM;
    unsigned* rhpk_my = g_rhpk + (size_t)b0 * HDIM;

    #pragma unroll 1
    for (int t = 0; t < SEQ; t++) {
        // prefetch XG for this step
        float xa0 = *pxA0, xa1 = *pxA1, xb = *pxB;
        pxA0 += NG; pxA1 += NG; pxB += NG;

        // ---- load h (packed) -> Ahi/Alo ----
        #pragma unroll
        for (int q = 0; q < 8; q++) {
            uint2 w = *(const uint2*)(hpk_my + q * 512 + tid * 2);
            *(uint32_t*)(smem + OFF_AHI + q * WROW + tid * 4) = __byte_perm(w.x, w.y, 0x5410);
            *(uint32_t*)(smem + OFF_ALO + q * WROW + tid * 4) = __byte_perm(w.x, w.y, 0x7632);
        }
        __syncthreads();

        // ---- phase A mma: z|r preacts, N64; 2 passes (W_hi, W_lo), 4-term product ----
        {
            float acc0[4] = {0.f, 0.f, 0.f, 0.f};
            float acc1[4] = {0.f, 0.f, 0.f, 0.f};
            #pragma unroll 1
            for (int p = 0; p < 2; p++) {
                uint32_t bb = p ? bZL : bZH;
                #pragma unroll
                for (int k16 = 0; k16 < 16; k16++) {
                    uint32_t off = (uint32_t)(k16 * 32);
                    uint32_t a[4], b[4];
                    LDM_X4(a[0], a[1], a[2], a[3], aA + off);
                    LDM_X4(b[0], b[1], b[2], b[3], bb + off);
                    MMA16816(acc0, a, b);
                    MMA16816(acc1, a, b + 2);
                }
            }
            int n0w = nsA * 16;
            *(float2*)&CRED(credf, kh, crow, n0w + ccol) =
                make_float2(acc0[0] + acc0[2], acc0[1] + acc0[3]);
            *(float2*)&CRED(credf, kh, crow, n0w + 8 + ccol) =
                make_float2(acc1[0] + acc1[2], acc1[1] + acc1[3]);
        }
        __syncthreads();

        // ---- combine A: sigmoid, publish z (smem) and r*h (global packed) ----
        {
            #pragma unroll
            for (int it = 0; it < 2; it++) {
                int b = cbA + it * 4;
                float s = CRED(credf, 0, b, cnA) + CRED(credf, 1, b, cnA)
                        + (it == 0 ? xa0 : xa1);
                float sig = 1.f / (1.f + __expf(-s));
                if (cnA < 32) {
                    zbuf[b * 32 + cnA] = sig;
                } else {
                    int jl = cnA - 32;
                    float rh = sig * h32[b * 32 + jl];
                    __nv_bfloat16 hi = __float2bfloat16(rh);
                    __nv_bfloat16 lo = __float2bfloat16(rh - __bfloat162float(hi));
                    rhpk_my[b * 512 + j0 + jl] =
                        (unsigned)__bfloat16_as_ushort(hi)
                        | ((unsigned)__bfloat16_as_ushort(lo) << 16);
                }
            }
        }
        gbar(&g_cnt, tgt); tgt += NBLK2;

        // ---- load rh (packed) -> Ahi/Alo ----
        #pragma unroll
        for (int q = 0; q < 8; q++) {
            uint2 w = *(const uint2*)(rhpk_my + q * 512 + tid * 2);
            *(uint32_t*)(smem + OFF_AHI + q * WROW + tid * 4) = __byte_perm(w.x, w.y, 0x5410);
            *(uint32_t*)(smem + OFF_ALO + q * WROW + tid * 4) = __byte_perm(w.x, w.y, 0x7632);
        }
        __syncthreads();

        // ---- phase B mma: h~ preacts, N32; 2 passes ----
        {
            float acc[4] = {0.f, 0.f, 0.f, 0.f};
            #pragma unroll 1
            for (int p = 0; p < 2; p++) {
                uint32_t bb = p ? bWL : bWH;
                #pragma unroll
                for (int k16 = 0; k16 < 16; k16++) {
                    uint32_t off = (uint32_t)(k16 * 32);
                    uint32_t a[4], b[2];
                    LDM_X4(a[0], a[1], a[2], a[3], aA + off);
                    LDM_X2(b[0], b[1], bb + off);
                    MMA16816(acc, a, b);
                }
            }
            int n0w = (wid & 3) * 8;
            *(float2*)&CRED(credf, kh, crow, n0w + ccol) =
                make_float2(acc[0] + acc[2], acc[1] + acc[3]);
        }
        __syncthreads();

        // ---- combine B: tanh, blend, publish h ----
        {
            float s = CRED(credf, 0, cbB, cjB) + CRED(credf, 1, cbB, cjB) + xb;
            float ht = tanhf(s);
            float hp = h32[tid];
            float z  = zbuf[tid];
            float hn = hp + z * (ht - hp);
            h32[tid] = hn;
            __nv_bfloat16 hi = __float2bfloat16(hn);
            __nv_bfloat16 lo = __float2bfloat16(hn - __bfloat162float(hi));
            hpk_my[cbB * 512 + j0 + cjB] =
                (unsigned)__bfloat16_as_ushort(hi) | ((unsigned)__bfloat16_as_ushort(lo) << 16);
            size_t hrow = ((size_t)(b0 + cbB) * SEQ + t) * HDIM + j0 + cjB;
            g_Hh[hrow] = hi;
            g_Hl[hrow] = lo;
            if (t == SEQ - 1)
                out[(size_t)BATCH * SEQ * BDIM + (b0 + cbB) * HDIM + j0 + cjB] = hn;
        }
        gbar(&g_cnt, tgt); tgt += NBLK2;
    }
}

// =====================================================================================
extern "C" void kernel_launch(void* const* d_in, const int* in_sizes, int n_in,
                              void* d_out, int out_size)
{
    (void)in_sizes; (void)n_in; (void)out_size;
    const float* x  = (const float*)d_in[0];
    const float* Wz = (const float*)d_in[1];
    const float* bz = (const float*)d_in[2];
    const float* Wr = (const float*)d_in[3];
    const float* br = (const float*)d_in[4];
    const float* Wh = (const float*)d_in[5];
    const float* bh = (const float*)d_in[6];
    const float* Wb = (const float*)d_in[7];
    const float* bb = (const float*)d_in[8];
    float* out = (float*)d_out;

    cudaFuncSetAttribute(recurrent_tc_kernel,
                         cudaFuncAttributeMaxDynamicSharedMemorySize, SMEM2_TOTAL);
    cudaFuncSetAttribute(gemm_mma_kernel,
                         cudaFuncAttributeMaxDynamicSharedMemorySize, GEMM_SMEM);

    __nv_bfloat16 *Xh, *Xl, *Wxh, *Wxl, *Hh, *Hl, *Wbh, *Wbl;
    float *XG, *bcat;
    unsigned* cntp;
    cudaGetSymbolAddress((void**)&Xh,  g_Xh);
    cudaGetSymbolAddress((void**)&Xl,  g_Xl);
    cudaGetSymbolAddress((void**)&Wxh, g_Wxh);
    cudaGetSymbolAddress((void**)&Wxl, g_Wxl);
    cudaGetSymbolAddress((void**)&Hh,  g_Hh);
    cudaGetSymbolAddress((void**)&Hl,  g_Hl);
    cudaGetSymbolAddress((void**)&Wbh, g_Wbh);
    cudaGetSymbolAddress((void**)&Wbl, g_Wbl);
    cudaGetSymbolAddress((void**)&XG,  g_XG);
    cudaGetSymbolAddress((void**)&bcat, g_bcat);
    cudaGetSymbolAddress((void**)&cntp, g_cnt);

    // Prep: bf16 hi/lo splits
    prep_wx_kernel<<<(NG * XPART + 255) / 256, 256>>>(Wz, Wr, Wh, bz, br, bh);
    prep_wb_kernel<<<(BDIM * HDIM + 255) / 256, 256>>>(Wb);
    prep_x_kernel<<<(M_TOTAL * XPART / 4) / 256, 256>>>(x);

    // Stage 1: XG = xcat @ Wx^T + bcat
    gemm_mma_kernel<<<dim3(NG / 256, M_TOTAL / 128), 256, GEMM_SMEM>>>(
        Xh, Xl, XPART, Wxh, Wxl, XPART, bcat, XG, NG, XPART / 32);

    // Stage 2: persistent tensor-core recurrence (writes g_Hh/g_Hl + h_fin tail)
    cudaMemsetAsync(cntp, 0, sizeof(unsigned));
    recurrent_tc_kernel<<<NBLK2, 256, SMEM2_TOTAL>>>(Wz, Wr, Wh, out);

    // Stage 3: out = H @ Wb^T + bb
    gemm_mma_kernel<<<dim3(BDIM / 256, M_TOTAL / 128), 256, GEMM_SMEM>>>(
        Hh, Hl, HDIM, Wbh, Wbl, HDIM, bb, out, BDIM, HDIM / 32);
}

// round 8
// speedup vs baseline: 2.0165x; 1.1077x over previous
#include <cuda_runtime.h>
#include <cuda_bf16.h>
#include <cstdint>
#include <cstddef>

// Problem constants
#define BATCH   64
#define SEQ     2048
#define IDIM    256
#define HDIM    512
#define BDIM    256
#define INDIM   1280     // 3*IDIM + HDIM
#define XPART   768      // 3*IDIM
#define M_TOTAL (BATCH * SEQ)   // 131072
#define NG      1536     // 3 gates * HDIM

#define NBLK2   128      // persistent recurrent grid (1 CTA/SM -> co-resident)

// -------------------- scratch (static __device__, allocation-free) --------------------
__device__ float g_XG[(size_t)M_TOTAL * NG];        // [b*SEQ+t][1536]: xz | xr | xh pre-acts
__device__ unsigned g_cnt8[8 * 32];                 // per-batch-slab barrier counters (padded)

// packed bf16 hi|lo exchange buffers (u32 = hi | lo<<16)
__device__ unsigned g_hpk [BATCH * HDIM];           // h_t
__device__ unsigned g_rhpk[BATCH * HDIM];           // r*h

// bf16 split operands
__device__ __nv_bfloat16 g_Xh[(size_t)M_TOTAL * XPART];   // x concat hi, [b*SEQ+t][768]
__device__ __nv_bfloat16 g_Xl[(size_t)M_TOTAL * XPART];
__device__ __nv_bfloat16 g_Wxh[(size_t)NG * XPART];       // [1536][768] x-part of Wz|Wr|Wh
__device__ __nv_bfloat16 g_Wxl[(size_t)NG * XPART];
__device__ __nv_bfloat16 g_Hh[(size_t)M_TOTAL * HDIM];    // hidden states, [b*SEQ+t][512]
__device__ __nv_bfloat16 g_Hl[(size_t)M_TOTAL * HDIM];
__device__ __nv_bfloat16 g_Wbh[(size_t)BDIM * HDIM];
__device__ __nv_bfloat16 g_Wbl[(size_t)BDIM * HDIM];
__device__ float g_bcat[NG];

// =====================================================================================
// MMA / ldmatrix / cp.async macros (portable sm_80+ PTX)
// =====================================================================================
#define LDM_X4(r0, r1, r2, r3, a) \
    asm volatile("ldmatrix.sync.aligned.m8n8.x4.shared.b16 {%0,%1,%2,%3}, [%4];" \
                 : "=r"(r0), "=r"(r1), "=r"(r2), "=r"(r3) : "r"(a))
#define LDM_X2(r0, r1, a) \
    asm volatile("ldmatrix.sync.aligned.m8n8.x2.shared.b16 {%0,%1}, [%2];" \
                 : "=r"(r0), "=r"(r1) : "r"(a))
#define MMA16816(d, a, b) \
    asm volatile("mma.sync.aligned.m16n8k16.row.col.f32.bf16.bf16.f32 " \
                 "{%0,%1,%2,%3}, {%4,%5,%6,%7}, {%8,%9}, {%0,%1,%2,%3};" \
                 : "+f"((d)[0]), "+f"((d)[1]), "+f"((d)[2]), "+f"((d)[3]) \
                 : "r"((a)[0]), "r"((a)[1]), "r"((a)[2]), "r"((a)[3]), \
                   "r"((b)[0]), "r"((b)[1]))
#define CP_ASYNC16(dst, src) \
    asm volatile("cp.async.cg.shared.global [%0], [%1], 16;" :: "r"(dst), "l"(src))
#define CP_COMMIT() asm volatile("cp.async.commit_group;" ::: "memory")
#define CP_WAIT1()  asm volatile("cp.async.wait_group 1;" ::: "memory")
#define CP_WAIT0()  asm volatile("cp.async.wait_group 0;" ::: "memory")

__device__ __forceinline__ uint32_t smem_u32(const void* p) {
    uint32_t a;
    asm("{ .reg .u64 t; cvta.to.shared.u64 t, %1; cvt.u32.u64 %0, t; }" : "=r"(a) : "l"(p));
    return a;
}

// =====================================================================================
// Prep kernels: build bf16 hi/lo split operands
// =====================================================================================
__global__ void __launch_bounds__(256) prep_wx_kernel(
    const float* __restrict__ Wz, const float* __restrict__ Wr, const float* __restrict__ Wh,
    const float* __restrict__ bz, const float* __restrict__ br, const float* __restrict__ bh)
{
    int idx = blockIdx.x * 256 + threadIdx.x;
    if (idx < NG * XPART) {
        int j = idx / XPART, k = idx - j * XPART;
        int gate = j >> 9, jj = j & 511;
        const float* W = (gate == 0) ? Wz : (gate == 1) ? Wr : Wh;
        float v = W[(size_t)jj * INDIM + k];
        __nv_bfloat16 hi = __float2bfloat16(v);
        __nv_bfloat16 lo = __float2bfloat16(v - __bfloat162float(hi));
        g_Wxh[idx] = hi; g_Wxl[idx] = lo;
    }
    if (idx < NG) {
        g_bcat[idx] = (idx < 512) ? bz[idx] : (idx < 1024) ? br[idx - 512] : bh[idx - 1024];
    }
}

__global__ void __launch_bounds__(256) prep_wb_kernel(const float* __restrict__ Wb)
{
    int idx = blockIdx.x * 256 + threadIdx.x;
    if (idx < BDIM * HDIM) {
        float v = Wb[idx];
        __nv_bfloat16 hi = __float2bfloat16(v);
        __nv_bfloat16 lo = __float2bfloat16(v - __bfloat162float(hi));
        g_Wbh[idx] = hi; g_Wbl[idx] = lo;
    }
}

// x (b, s, t, i) -> Xh/Xl[(b*SEQ+t)*768 + s*256 + i]
__global__ void __launch_bounds__(256) prep_x_kernel(const float* __restrict__ x)
{
    int idx = blockIdx.x * 256 + threadIdx.x;      // one float4
    size_t e = (size_t)idx * 4;
    int b = (int)(e / 1572864);                    // 3*2048*256
    int r = (int)(e - (size_t)b * 1572864);
    int s = r / 524288;                            // 2048*256
    int r2 = r - s * 524288;
    int t = r2 >> 8, i = r2 & 255;
    float4 v = *(const float4*)(x + e);
    size_t dst = ((size_t)b * SEQ + t) * XPART + s * 256 + i;
    __nv_bfloat16 hx = __float2bfloat16(v.x), hy = __float2bfloat16(v.y);
    __nv_bfloat16 hz = __float2bfloat16(v.z), hw = __float2bfloat16(v.w);
    *(__nv_bfloat162*)(g_Xh + dst)     = __nv_bfloat162(hx, hy);
    *(__nv_bfloat162*)(g_Xh + dst + 2) = __nv_bfloat162(hz, hw);
    *(__nv_bfloat162*)(g_Xl + dst)     = __nv_bfloat162(
        __float2bfloat16(v.x - __bfloat162float(hx)), __float2bfloat16(v.y - __bfloat162float(hy)));
    *(__nv_bfloat162*)(g_Xl + dst + 2) = __nv_bfloat162(
        __float2bfloat16(v.z - __bfloat162float(hz)), __float2bfloat16(v.w - __bfloat162float(hw)));
}

// =====================================================================================
// cp.async double-buffered mma.sync GEMM (stages 1 & 3).
//   C[m][n] = bias[n] + sum_k A[m][k]*B[n][k],  augmented K: AhBh | AhBl | AlBh
//   CTA tile 128M x 128N x BK32, 8 warps (2M x 4N), warp tile 64x32, 2 CTAs/SM.
// =====================================================================================
#define GSTRIDE 80                      // smem row stride bytes (32 bf16 data + 8 pad)
#define G_ABYTES (128 * GSTRIDE)        // 10240
#define G_STAGE  (2 * G_ABYTES)         // 20480 (A + B)
#define GEMM_SMEM (2 * G_STAGE)         // 40960

__global__ void __launch_bounds__(256, 2) gemm_mma_kernel(
    const __nv_bfloat16* __restrict__ Ah, const __nv_bfloat16* __restrict__ Al, int lda,
    const __nv_bfloat16* __restrict__ Bh, const __nv_bfloat16* __restrict__ Bl, int ldb,
    const float* __restrict__ bias, float* __restrict__ C, int ldc, int K32)
{
    extern __shared__ char gsm[];
    const uint32_t sbase = smem_u32(gsm);

    const int tid  = threadIdx.x;
    const int wid  = tid >> 5;
    const int lane = tid & 31;
    const int n0   = blockIdx.x * 128;
    const int m0   = blockIdx.y * 128;
    const int m0w  = (wid & 1) * 64;
    const int n0w  = (wid >> 1) * 32;

    const int NC = 3 * K32;

    // ldmatrix per-lane address components (byte offsets within a stage)
    const uint32_t a_base = (uint32_t)(((lane & 7) + ((lane >> 3) & 1) * 8) * GSTRIDE
                                       + ((lane >> 4) & 1) * 16);
    const uint32_t b_base = (uint32_t)(((lane & 7) + ((lane >> 4) & 1) * 8) * GSTRIDE
                                       + ((lane >> 3) & 1) * 16);

    float acc[4][4][4];
    #pragma unroll
    for (int i = 0; i < 4; i++)
        #pragma unroll
        for (int j = 0; j < 4; j++)
            #pragma unroll
            for (int q = 0; q < 4; q++) acc[i][j][q] = 0.f;

    // ---- async tile loader: chunk c -> stage buf (A: 512 units, B: 512 units) ----
    auto issue = [&](int c) {
        const int ph = c / K32;
        const int kk = (c - ph * K32) * 32;
        const __nv_bfloat16* Asrc = (ph < 2) ? Ah : Al;
        const __nv_bfloat16* Bsrc = (ph == 1) ? Bl : Bh;
        const uint32_t sb = sbase + (uint32_t)((c & 1) * G_STAGE);
        #pragma unroll
        for (int i = 0; i < 2; i++) {
            int u = tid + i * 256;
            int row = u >> 2, c16 = u & 3;
            CP_ASYNC16(sb + row * GSTRIDE + c16 * 16,
                       Asrc + (size_t)(m0 + row) * lda + kk + c16 * 8);
        }
        #pragma unroll
        for (int i = 0; i < 2; i++) {
            int u = tid + i * 256;
            int row = u >> 2, c16 = u & 3;
            CP_ASYNC16(sb + G_ABYTES + row * GSTRIDE + c16 * 16,
                       Bsrc + (size_t)(n0 + row) * ldb + kk + c16 * 8);
        }
        CP_COMMIT();
    };

    issue(0);

    #pragma unroll 1
    for (int c = 0; c < NC; c++) {
        if (c + 1 < NC) { issue(c + 1); CP_WAIT1(); } else { CP_WAIT0(); }
        __syncthreads();

        const uint32_t sb = sbase + (uint32_t)((c & 1) * G_STAGE);
        const uint32_t sA = sb + (uint32_t)(m0w * GSTRIDE) + a_base;
        const uint32_t sB = sb + G_ABYTES + (uint32_t)(n0w * GSTRIDE) + b_base;

        #pragma unroll
        for (int ks = 0; ks < 2; ks++) {
            uint32_t af[4][4];
            #pragma unroll
            for (int mb = 0; mb < 4; mb++)
                LDM_X4(af[mb][0], af[mb][1], af[mb][2], af[mb][3],
                       sA + (uint32_t)(mb * 16 * GSTRIDE + ks * 32));
            uint32_t bf[4][2];
            #pragma unroll
            for (int q = 0; q < 2; q++)
                LDM_X4(bf[2 * q][0], bf[2 * q][1], bf[2 * q + 1][0], bf[2 * q + 1][1],
                       sB + (uint32_t)(q * 16 * GSTRIDE + ks * 32));
            #pragma unroll
            for (int mb = 0; mb < 4; mb++)
                #pragma unroll
                for (int nb = 0; nb < 4; nb++)
                    MMA16816(acc[mb][nb], af[mb], bf[nb]);
        }
        __syncthreads();
    }

    // epilogue
    const int g   = lane >> 2;
    const int tig = lane & 3;
    #pragma unroll
    for (int mb = 0; mb < 4; mb++) {
        #pragma unroll
        for (int nb = 0; nb < 4; nb++) {
            int col = n0 + n0w + nb * 8 + tig * 2;
            float b0 = bias[col], b1 = bias[col + 1];
            int r0 = m0 + m0w + mb * 16 + g;
            *(float2*)(C + (size_t)r0 * ldc + col) =
                make_float2(acc[mb][nb][0] + b0, acc[mb][nb][1] + b1);
            *(float2*)(C + (size_t)(r0 + 8) * ldc + col) =
                make_float2(acc[mb][nb][2] + b0, acc[mb][nb][3] + b1);
        }
    }
}

// =====================================================================================
// Stage 2: persistent TENSOR-CORE recurrence, M-packed hi/lo (rows 0-7 hi, 8-15 lo).
//   128 CTAs = 8 bslabs x 16 jslabs. Per-batch-slab barriers (16 arrivals each).
//   A-fragments ldmatrix'd once per k16 and reused across the hi/lo B passes.
// =====================================================================================
#define WROW   1040                 // weight/A smem row stride in bytes (520 bf16)
#define OFF_WZRH 0
#define OFF_WZRL (OFF_WZRH + 64*WROW)
#define OFF_WHH  (OFF_WZRL + 64*WROW)
#define OFF_WHL  (OFF_WHH  + 32*WROW)
#define OFF_AHI  (OFF_WHL  + 32*WROW)
#define OFF_ALO  (OFF_AHI  + 8*WROW)
#define OFF_CRED (OFF_ALO  + 8*WROW)
#define OFF_H32  (OFF_CRED + 2*8*66*4)
#define OFF_ZB   (OFF_H32  + 1024)
#define SMEM2_TOTAL (OFF_ZB + 1024)

#define CRED(p, h, r, n) p[((h) * 8 + (r)) * 66 + (n)]

// per-slab barrier: 16 arrivals, monotonic counter
__device__ __forceinline__ void gbar16(unsigned* cnt, unsigned target) {
    __syncthreads();
    if (threadIdx.x == 0) {
        asm volatile("red.release.gpu.global.add.u32 [%0], %1;" :: "l"(cnt), "r"(1u));
        unsigned c;
        do {
            asm volatile("ld.acquire.gpu.global.u32 %0, [%1];" : "=r"(c) : "l"(cnt));
        } while ((int)(c - target) < 0);
    }
    __syncthreads();
}

__global__ void __launch_bounds__(256, 1) recurrent_tc_kernel(
    const float* __restrict__ Wz, const float* __restrict__ Wr, const float* __restrict__ Wh,
    float* __restrict__ out)
{
    extern __shared__ char smem[];
    const uint32_t sbase = smem_u32(smem);
    float* credf = (float*)(smem + OFF_CRED);
    float* h32   = (float*)(smem + OFF_H32);
    float* zbuf  = (float*)(smem + OFF_ZB);

    const int tid  = threadIdx.x;
    const int wid  = tid >> 5;
    const int lane = tid & 31;
    const int blk  = blockIdx.x;
    const int bslab = blk >> 4;
    const int b0   = bslab * 8;
    const int j0   = (blk & 15) * 32;
    unsigned* mycnt = &g_cnt8[bslab * 32];

    // ---- load + split weights into smem (one-time) ----
    for (int e = tid; e < 64 * 512; e += 256) {
        int row = e >> 9, k = e & 511;
        const float* W = (row < 32) ? Wz : Wr;
        float v = W[(size_t)(j0 + (row & 31)) * INDIM + XPART + k];
        __nv_bfloat16 hi = __float2bfloat16(v);
        __nv_bfloat16 lo = __float2bfloat16(v - __bfloat162float(hi));
        *(__nv_bfloat16*)(smem + OFF_WZRH + row * WROW + k * 2) = hi;
        *(__nv_bfloat16*)(smem + OFF_WZRL + row * WROW + k * 2) = lo;
    }
    for (int e = tid; e < 32 * 512; e += 256) {
        int row = e >> 9, k = e & 511;
        float v = Wh[(size_t)(j0 + row) * INDIM + XPART + k];
        __nv_bfloat16 hi = __float2bfloat16(v);
        __nv_bfloat16 lo = __float2bfloat16(v - __bfloat162float(hi));
        *(__nv_bfloat16*)(smem + OFF_WHH + row * WROW + k * 2) = hi;
        *(__nv_bfloat16*)(smem + OFF_WHL + row * WROW + k * 2) = lo;
    }
    h32[tid] = 0.f;
    g_hpk[(b0 + (tid >> 5)) * HDIM + j0 + (tid & 31)] = 0u;

    unsigned tgt = 16;
    gbar16(mycnt, tgt); tgt += 16;

    // ---- per-warp fragment address bases ----
    const int kh  = wid >> 2;                // K half: 0 -> k[0,256), 1 -> k[256,512)
    const int khB = kh * 512;                // byte offset of K half
    const int arow  = lane & 7;
    const int isLo  = (lane >> 3) & 1;       // lanes 8-15 / 24-31 -> lo rows
    const uint32_t akof = (uint32_t)(((lane >> 4) & 1) * 16);
    const uint32_t aA = sbase + (isLo ? OFF_ALO : OFF_AHI) + arow * WROW + akof + khB;

    const int nsA = wid & 3;                 // phase A N16 slice
    const int browA = nsA * 16 + (lane & 7) + ((lane >> 4) & 1) * 8;
    const uint32_t bkofA = (uint32_t)(((lane >> 3) & 1) * 16);
    const uint32_t bZH = sbase + OFF_WZRH + browA * WROW + bkofA + khB;
    const uint32_t bZL = sbase + OFF_WZRL + browA * WROW + bkofA + khB;

    const int browB = (wid & 3) * 8 + (lane & 7);   // phase B N8 slice
    const uint32_t bkofB = (uint32_t)(((lane >> 3) & 1) * 16);
    const uint32_t bWH = sbase + OFF_WHH + browB * WROW + bkofB + khB;
    const uint32_t bWL = sbase + OFF_WHL + browB * WROW + bkofB + khB;

    // combine mappings + running XG pointers
    const int cbA = tid >> 6;                // combine A: batches cbA and cbA+4
    const int cnA = tid & 63;                // 0..31 -> z, 32..63 -> r
    const int colA = (cnA < 32) ? (j0 + cnA) : (512 + j0 + (cnA - 32));
    const float* pxA0 = g_XG + (size_t)(b0 + cbA)     * SEQ * NG + colA;
    const float* pxA1 = g_XG + (size_t)(b0 + cbA + 4) * SEQ * NG + colA;
    const int cbB = tid >> 5, cjB = tid & 31;
    const float* pxB = g_XG + (size_t)(b0 + cbB) * SEQ * NG + 1024 + j0 + cjB;

    const int crow = lane >> 2;              // C frag row (0..7)
    const int ccol = (lane & 3) * 2;

    unsigned* hpk_my  = g_hpk  + (size_t)b0 * HDIM;
    unsigned* rhpk_my = g_rhpk + (size_t)b0 * HDIM;

    #pragma unroll 1
    for (int t = 0; t < SEQ; t++) {
        // prefetch XG for this step
        float xa0 = *pxA0, xa1 = *pxA1, xb = *pxB;
        pxA0 += NG; pxA1 += NG; pxB += NG;

        // ---- load h (packed) -> Ahi/Alo ----
        #pragma unroll
        for (int q = 0; q < 8; q++) {
            uint2 w = *(const uint2*)(hpk_my + q * 512 + tid * 2);
            *(uint32_t*)(smem + OFF_AHI + q * WROW + tid * 4) = __byte_perm(w.x, w.y, 0x5410);
            *(uint32_t*)(smem + OFF_ALO + q * WROW + tid * 4) = __byte_perm(w.x, w.y, 0x7632);
        }
        __syncthreads();

        // ---- phase A mma: z|r preacts, N64; A-frag loaded once per k16 ----
        {
            float acc0[4] = {0.f, 0.f, 0.f, 0.f};
            float acc1[4] = {0.f, 0.f, 0.f, 0.f};
            #pragma unroll
            for (int k16 = 0; k16 < 16; k16++) {
                uint32_t off = (uint32_t)(k16 * 32);
                uint32_t a[4], bh[4], bl[4];
                LDM_X4(a[0], a[1], a[2], a[3], aA + off);
                LDM_X4(bh[0], bh[1], bh[2], bh[3], bZH + off);
                LDM_X4(bl[0], bl[1], bl[2], bl[3], bZL + off);
                MMA16816(acc0, a, bh);
                MMA16816(acc1, a, bh + 2);
                MMA16816(acc0, a, bl);
                MMA16816(acc1, a, bl + 2);
            }
            int n0w = nsA * 16;
            *(float2*)&CRED(credf, kh, crow, n0w + ccol) =
                make_float2(acc0[0] + acc0[2], acc0[1] + acc0[3]);
            *(float2*)&CRED(credf, kh, crow, n0w + 8 + ccol) =
                make_float2(acc1[0] + acc1[2], acc1[1] + acc1[3]);
        }
        __syncthreads();

        // ---- combine A: sigmoid, publish z (smem) and r*h (global packed) ----
        {
            #pragma unroll
            for (int it = 0; it < 2; it++) {
                int b = cbA + it * 4;
                float s = CRED(credf, 0, b, cnA) + CRED(credf, 1, b, cnA)
                        + (it == 0 ? xa0 : xa1);
                float sig = 1.f / (1.f + __expf(-s));
                if (cnA < 32) {
                    zbuf[b * 32 + cnA] = sig;
                } else {
                    int jl = cnA - 32;
                    float rh = sig * h32[b * 32 + jl];
                    __nv_bfloat16 hi = __float2bfloat16(rh);
                    __nv_bfloat16 lo = __float2bfloat16(rh - __bfloat162float(hi));
                    rhpk_my[b * 512 + j0 + jl] =
                        (unsigned)__bfloat16_as_ushort(hi)
                        | ((unsigned)__bfloat16_as_ushort(lo) << 16);
                }
            }
        }
        gbar16(mycnt, tgt); tgt += 16;

        // ---- load rh (packed) -> Ahi/Alo ----
        #pragma unroll
        for (int q = 0; q < 8; q++) {
            uint2 w = *(const uint2*)(rhpk_my + q * 512 + tid * 2);
            *(uint32_t*)(smem + OFF_AHI + q * WROW + tid * 4) = __byte_perm(w.x, w.y, 0x5410);
            *(uint32_t*)(smem + OFF_ALO + q * WROW + tid * 4) = __byte_perm(w.x, w.y, 0x7632);
        }
        __syncthreads();

        // ---- phase B mma: h~ preacts, N32; A-frag loaded once per k16 ----
        {
            float acc[4] = {0.f, 0.f, 0.f, 0.f};
            #pragma unroll
            for (int k16 = 0; k16 < 16; k16++) {
                uint32_t off = (uint32_t)(k16 * 32);
                uint32_t a[4], bh[2], bl[2];
                LDM_X4(a[0], a[1], a[2], a[3], aA + off);
                LDM_X2(bh[0], bh[1], bWH + off);
                LDM_X2(bl[0], bl[1], bWL + off);
                MMA16816(acc, a, bh);
                MMA16816(acc, a, bl);
            }
            int n0w = (wid & 3) * 8;
            *(float2*)&CRED(credf, kh, crow, n0w + ccol) =
                make_float2(acc[0] + acc[2], acc[1] + acc[3]);
        }
        __syncthreads();

        // ---- combine B: tanh, blend, publish h ----
        {
            float s = CRED(credf, 0, cbB, cjB) + CRED(credf, 1, cbB, cjB) + xb;
            float ht = tanhf(s);
            float hp = h32[tid];
            float z  = zbuf[tid];
            float hn = hp + z * (ht - hp);
            h32[tid] = hn;
            __nv_bfloat16 hi = __float2bfloat16(hn);
            __nv_bfloat16 lo = __float2bfloat16(hn - __bfloat162float(hi));
            hpk_my[cbB * 512 + j0 + cjB] =
                (unsigned)__bfloat16_as_ushort(hi) | ((unsigned)__bfloat16_as_ushort(lo) << 16);
            size_t hrow = ((size_t)(b0 + cbB) * SEQ + t) * HDIM + j0 + cjB;
            g_Hh[hrow] = hi;
            g_Hl[hrow] = lo;
            if (t == SEQ - 1)
                out[(size_t)BATCH * SEQ * BDIM + (b0 + cbB) * HDIM + j0 + cjB] = hn;
        }
        gbar16(mycnt, tgt); tgt += 16;
    }
}

// =====================================================================================
extern "C" void kernel_launch(void* const* d_in, const int* in_sizes, int n_in,
                              void* d_out, int out_size)
{
    (void)in_sizes; (void)n_in; (void)out_size;
    const float* x  = (const float*)d_in[0];
    const float* Wz = (const float*)d_in[1];
    const float* bz = (const float*)d_in[2];
    const float* Wr = (const float*)d_in[3];
    const float* br = (const float*)d_in[4];
    const float* Wh = (const float*)d_in[5];
    const float* bh = (const float*)d_in[6];
    const float* Wb = (const float*)d_in[7];
    const float* bb = (const float*)d_in[8];
    float* out = (float*)d_out;

    cudaFuncSetAttribute(recurrent_tc_kernel,
                         cudaFuncAttributeMaxDynamicSharedMemorySize, SMEM2_TOTAL);
    cudaFuncSetAttribute(gemm_mma_kernel,
                         cudaFuncAttributeMaxDynamicSharedMemorySize, GEMM_SMEM);

    __nv_bfloat16 *Xh, *Xl, *Wxh, *Wxl, *Hh, *Hl, *Wbh, *Wbl;
    float *XG, *bcat;
    unsigned* cntp;
    cudaGetSymbolAddress((void**)&Xh,  g_Xh);
    cudaGetSymbolAddress((void**)&Xl,  g_Xl);
    cudaGetSymbolAddress((void**)&Wxh, g_Wxh);
    cudaGetSymbolAddress((void**)&Wxl, g_Wxl);
    cudaGetSymbolAddress((void**)&Hh,  g_Hh);
    cudaGetSymbolAddress((void**)&Hl,  g_Hl);
    cudaGetSymbolAddress((void**)&Wbh, g_Wbh);
    cudaGetSymbolAddress((void**)&Wbl, g_Wbl);
    cudaGetSymbolAddress((void**)&XG,  g_XG);
    cudaGetSymbolAddress((void**)&bcat, g_bcat);
    cudaGetSymbolAddress((void**)&cntp, g_cnt8);

    // Prep: bf16 hi/lo splits
    prep_wx_kernel<<<(NG * XPART + 255) / 256, 256>>>(Wz, Wr, Wh, bz, br, bh);
    prep_wb_kernel<<<(BDIM * HDIM + 255) / 256, 256>>>(Wb);
    prep_x_kernel<<<(M_TOTAL * XPART / 4) / 256, 256>>>(x);

    // Stage 1: XG = xcat @ Wx^T + bcat
    gemm_mma_kernel<<<dim3(NG / 128, M_TOTAL / 128), 256, GEMM_SMEM>>>(
        Xh, Xl, XPART, Wxh, Wxl, XPART, bcat, XG, NG, XPART / 32);

    // Stage 2: persistent tensor-core recurrence (writes g_Hh/g_Hl + h_fin tail)
    cudaMemsetAsync(cntp, 0, 8 * 32 * sizeof(unsigned));
    recurrent_tc_kernel<<<NBLK2, 256, SMEM2_TOTAL>>>(Wz, Wr, Wh, out);

    // Stage 3: out = H @ Wb^T + bb
    gemm_mma_kernel<<<dim3(BDIM / 128, M_TOTAL / 128), 256, GEMM_SMEM>>>(
        Hh, Hl, HDIM, Wbh, Wbl, HDIM, bb, out, BDIM, HDIM / 32);
}